// round 2
// baseline (speedup 1.0000x reference)
#include <cuda_runtime.h>
#include <math.h>

#define BATCH 512
#define CIN   1024
#define CMID  512
#define HW2   196
#define EMBD  1024
#define NCOL  (BATCH * HW2)   // 100352 = 784 * 128

// ---------------- scratch (device globals; no allocations allowed) ----------
__device__ float g_attr1[8 * 512];
__device__ float g_attr2[8 * 512];
__device__ float g_attlog[NCOL];
__device__ float g_attp[NCOL];
__device__ float g_feat[BATCH * 1024];
__device__ float g_h1[BATCH * 512];
__device__ float g_mask[BATCH * 1024];

// ---------------- attr tables: 8 x 512, tiny -------------------------------
__global__ void attr_kernel(const float* __restrict__ emb,
                            const float* __restrict__ Wt1, const float* __restrict__ bt1,
                            const float* __restrict__ Wt2, const float* __restrict__ bt2) {
    int a = blockIdx.x;            // 0..7
    __shared__ float e[512];
    int tid = threadIdx.x;         // 256
    e[tid]       = emb[a * 512 + tid];
    e[tid + 256] = emb[a * 512 + tid + 256];
    __syncthreads();
    int warp = tid >> 5, lane = tid & 31;
    for (int o = warp; o < 512; o += 8) {
        float s1 = 0.f, s2 = 0.f;
        for (int k = lane; k < 512; k += 32) {
            float ev = e[k];
            s1 = fmaf(ev, Wt1[o * 512 + k], s1);
            s2 = fmaf(ev, Wt2[o * 512 + k], s2);
        }
        #pragma unroll
        for (int off = 16; off; off >>= 1) {
            s1 += __shfl_down_sync(0xffffffffu, s1, off);
            s2 += __shfl_down_sync(0xffffffffu, s2, off);
        }
        if (lane == 0) {
            g_attr1[a * 512 + o] = tanhf(s1 + bt1[o]);
            g_attr2[a * 512 + o] = fmaxf(s2 + bt2[o], 0.f);
        }
    }
}

__global__ void zero_attlog_kernel() {
    int i = blockIdx.x * blockDim.x + threadIdx.x;
    if (i < NCOL) g_attlog[i] = 0.f;
}

// ---------------- fused conv1x1 + BN + tanh + attn dot ---------------------
// GEMM: M=512 (o), N=100352 (n = b*196+hw), K=1024.
// Epilogue reduces over o with attr1[c[b]] weights -> atomicAdd into g_attlog.
__global__ void __launch_bounds__(256) conv_att_kernel(
    const float* __restrict__ x,   const float* __restrict__ Wc,
    const float* __restrict__ bc,  const float* __restrict__ gamma,
    const float* __restrict__ beta, const float* __restrict__ mean,
    const float* __restrict__ var, const int* __restrict__ cidx) {
    __shared__ float As[16][128];
    __shared__ float Bs[16][128];
    __shared__ float sSc[128], sBi[128];

    int tid = threadIdx.x;
    int n0 = blockIdx.x * 128;
    int m0 = blockIdx.y * 128;
    int tm = tid >> 4, tn = tid & 15;

    int aM = tid >> 2;          // 0..63 (and +64)
    int aK = (tid & 3) << 2;    // 0,4,8,12
    int bK = tid >> 5;          // 0..7 (and +8)
    int bN = (tid & 31) << 2;   // 0..124

    // column batch for this thread's B-load: its 4 columns never cross a
    // batch boundary (196 % 4 == 0, bN % 4 == 0)
    int n_load = n0 + bN;
    int b_load = n_load / HW2;
    int hw_load = n_load - b_load * HW2;
    const float* xb = x + (size_t)b_load * (CIN * HW2) + hw_load;
    const float* wb = Wc + (size_t)(m0 + aM) * CIN + aK;

    float acc[8][8];
    #pragma unroll
    for (int i = 0; i < 8; i++)
        #pragma unroll
        for (int j = 0; j < 8; j++) acc[i][j] = 0.f;

    for (int k0 = 0; k0 < CIN; k0 += 16) {
        #pragma unroll
        for (int r = 0; r < 2; r++) {
            float4 v = *(const float4*)(wb + (size_t)r * 64 * CIN + k0);
            int m = aM + r * 64;
            As[aK + 0][m] = v.x; As[aK + 1][m] = v.y;
            As[aK + 2][m] = v.z; As[aK + 3][m] = v.w;
        }
        #pragma unroll
        for (int r = 0; r < 2; r++) {
            int kk = bK + r * 8;
            float4 v = *(const float4*)(xb + (size_t)(k0 + kk) * HW2);
            *(float4*)&Bs[kk][bN] = v;
        }
        __syncthreads();
        #pragma unroll
        for (int kk = 0; kk < 16; kk++) {
            float a[8], b[8];
            *(float4*)&a[0] = *(const float4*)&As[kk][tm * 8];
            *(float4*)&a[4] = *(const float4*)&As[kk][tm * 8 + 4];
            *(float4*)&b[0] = *(const float4*)&Bs[kk][tn * 8];
            *(float4*)&b[4] = *(const float4*)&Bs[kk][tn * 8 + 4];
            #pragma unroll
            for (int i = 0; i < 8; i++)
                #pragma unroll
                for (int j = 0; j < 8; j++)
                    acc[i][j] = fmaf(a[i], b[j], acc[i][j]);
        }
        __syncthreads();
    }

    // per-channel fused BN affine:  out = acc*sc + ((bc-mean)*sc + beta)
    if (tid < 128) {
        int m = m0 + tid;
        float sc = gamma[m] * rsqrtf(var[m] + 1e-5f);
        sSc[tid] = sc;
        sBi[tid] = (bc[m] - mean[m]) * sc + beta[m];
    }
    __syncthreads();

    float s[8];
    #pragma unroll
    for (int j = 0; j < 8; j++) {
        int n = n0 + tn * 8 + j;
        int bb = n / HW2;
        int cb = cidx[bb];
        const float* aw = g_attr1 + cb * 512 + m0 + tm * 8;
        float acc_s = 0.f;
        #pragma unroll
        for (int i = 0; i < 8; i++) {
            float v = fmaf(acc[i][j], sSc[tm * 8 + i], sBi[tm * 8 + i]);
            acc_s = fmaf(aw[i], tanhf(v), acc_s);
        }
        s[j] = acc_s;
    }

    // cross-thread reduce over the 16 tm groups (reuse As as 16x128 buffer)
    float* red = &As[0][0];
    #pragma unroll
    for (int j = 0; j < 8; j++) red[tm * 128 + tn * 8 + j] = s[j];
    __syncthreads();
    if (tid < 128) {
        float t = 0.f;
        #pragma unroll
        for (int r = 0; r < 16; r++) t += red[r * 128 + tid];
        atomicAdd(&g_attlog[n0 + tid], t);
    }
}

// ---------------- spatial softmax per batch --------------------------------
__global__ void softmax_kernel() {
    int b = blockIdx.x, tid = threadIdx.x;   // 256 threads, 196 active
    __shared__ float sh[256];
    float v = (tid < HW2) ? g_attlog[b * HW2 + tid] * 0.044194173824159216f
                          : -1e30f;
    sh[tid] = v;
    __syncthreads();
    for (int s = 128; s; s >>= 1) {
        if (tid < s) sh[tid] = fmaxf(sh[tid], sh[tid + s]);
        __syncthreads();
    }
    float mx = sh[0];
    __syncthreads();
    float e = (tid < HW2) ? expf(v - mx) : 0.f;
    sh[tid] = e;
    __syncthreads();
    for (int s = 128; s; s >>= 1) {
        if (tid < s) sh[tid] += sh[tid + s];
        __syncthreads();
    }
    float inv = 1.f / sh[0];
    if (tid < HW2) g_attp[b * HW2 + tid] = e * inv;
}

// ---------------- feat[b,c] = sum_hw x[b,c,hw] * p[b,hw] -------------------
__global__ void feat_kernel(const float* __restrict__ x) {
    int b = blockIdx.x;
    __shared__ float p[HW2];
    int tid = threadIdx.x;
    if (tid < HW2) p[tid] = g_attp[b * HW2 + tid];
    __syncthreads();
    int warp = tid >> 5, lane = tid & 31;
    const float* xb = x + (size_t)b * (CIN * HW2);
    for (int cch = warp; cch < CIN; cch += 8) {
        float sum = 0.f;
        for (int hw = lane; hw < HW2; hw += 32)
            sum = fmaf(xb[cch * HW2 + hw], p[hw], sum);
        #pragma unroll
        for (int off = 16; off; off >>= 1)
            sum += __shfl_down_sync(0xffffffffu, sum, off);
        if (lane == 0) g_feat[b * CIN + cch] = sum;
    }
}

// ---------------- generic 64x64 GEMM: C = act(A @ W^T + bias) --------------
// MODE 0: A = g_h1 (stride K=512)
// MODE 1: A = concat(g_feat[1024] | g_attr2[c[m]][512]), K=1536
// MODE 2: A = g_feat * g_mask (stride K=1024)
// DST  0: g_h1   1: g_mask   2: param C
// ACT  0: none   1: relu     2: sigmoid
template <int MODE, int ACT, int DST>
__global__ void __launch_bounds__(256) gemm64_kernel(
    const float* __restrict__ W, const float* __restrict__ bias,
    float* __restrict__ Cout, int N, int K, const int* __restrict__ cidx) {
    __shared__ float As[16][64];
    __shared__ float Ws[16][64];
    int tid = threadIdx.x;
    int n0 = blockIdx.x * 64, m0 = blockIdx.y * 64;
    int lr = tid >> 2;          // 0..63
    int lk = (tid & 3) << 2;    // 0,4,8,12
    int tm = tid >> 4, tn = tid & 15;

    float acc[4][4];
    #pragma unroll
    for (int i = 0; i < 4; i++)
        #pragma unroll
        for (int j = 0; j < 4; j++) acc[i][j] = 0.f;

    for (int k0 = 0; k0 < K; k0 += 16) {
        int m = m0 + lr, k = k0 + lk;
        float4 av;
        if (MODE == 0) {
            av = *(const float4*)(g_h1 + (size_t)m * 512 + k);
        } else if (MODE == 1) {
            if (k < 1024) av = *(const float4*)(g_feat + (size_t)m * 1024 + k);
            else          av = *(const float4*)(g_attr2 + cidx[m] * 512 + (k - 1024));
        } else {
            float4 f = *(const float4*)(g_feat + (size_t)m * 1024 + k);
            float4 g = *(const float4*)(g_mask + (size_t)m * 1024 + k);
            av = make_float4(f.x * g.x, f.y * g.y, f.z * g.z, f.w * g.w);
        }
        As[lk + 0][lr] = av.x; As[lk + 1][lr] = av.y;
        As[lk + 2][lr] = av.z; As[lk + 3][lr] = av.w;

        float4 wv = *(const float4*)(W + (size_t)(n0 + lr) * K + k);
        Ws[lk + 0][lr] = wv.x; Ws[lk + 1][lr] = wv.y;
        Ws[lk + 2][lr] = wv.z; Ws[lk + 3][lr] = wv.w;
        __syncthreads();
        #pragma unroll
        for (int kk = 0; kk < 16; kk++) {
            float a[4], b[4];
            *(float4*)a = *(const float4*)&As[kk][tm * 4];
            *(float4*)b = *(const float4*)&Ws[kk][tn * 4];
            #pragma unroll
            for (int i = 0; i < 4; i++)
                #pragma unroll
                for (int j = 0; j < 4; j++)
                    acc[i][j] = fmaf(a[i], b[j], acc[i][j]);
        }
        __syncthreads();
    }

    float* Cp = (DST == 0) ? g_h1 : (DST == 1) ? g_mask : Cout;
    #pragma unroll
    for (int j = 0; j < 4; j++) {
        int n = n0 + tn * 4 + j;
        float bv = bias[n];
        #pragma unroll
        for (int i = 0; i < 4; i++) {
            int m = m0 + tm * 4 + i;
            float v = acc[i][j] + bv;
            if (ACT == 1) v = fmaxf(v, 0.f);
            else if (ACT == 2) v = 1.f / (1.f + expf(-v));
            Cp[(size_t)m * N + n] = v;
        }
    }
}

// ---------------- row-wise L2 normalize in place ----------------------------
__global__ void l2norm_kernel(float* __restrict__ out) {
    int b = blockIdx.x, tid = threadIdx.x;
    __shared__ float sh[256];
    float s = 0.f;
    for (int i = tid; i < EMBD; i += 256) {
        float v = out[(size_t)b * EMBD + i];
        s = fmaf(v, v, s);
    }
    sh[tid] = s;
    __syncthreads();
    for (int st = 128; st; st >>= 1) {
        if (tid < st) sh[tid] += sh[tid + st];
        __syncthreads();
    }
    float inv = 1.f / sqrtf(sh[0]);
    for (int i = tid; i < EMBD; i += 256) out[(size_t)b * EMBD + i] *= inv;
}

// ---------------- launch ----------------------------------------------------
extern "C" void kernel_launch(void* const* d_in, const int* in_sizes, int n_in,
                              void* d_out, int out_size) {
    const float* x        = (const float*)d_in[0];
    const int*   c        = (const int*)  d_in[1];
    const float* attr_emb = (const float*)d_in[2];
    const float* Wt1      = (const float*)d_in[3];
    const float* bt1      = (const float*)d_in[4];
    const float* Wc       = (const float*)d_in[5];
    const float* bc       = (const float*)d_in[6];
    const float* bn_gamma = (const float*)d_in[7];
    const float* bn_beta  = (const float*)d_in[8];
    const float* bn_mean  = (const float*)d_in[9];
    const float* bn_var   = (const float*)d_in[10];
    const float* Wt2      = (const float*)d_in[11];
    const float* bt2      = (const float*)d_in[12];
    const float* W1       = (const float*)d_in[13];
    const float* b1       = (const float*)d_in[14];
    const float* W2       = (const float*)d_in[15];
    const float* b2       = (const float*)d_in[16];
    const float* Wf       = (const float*)d_in[17];
    const float* bf       = (const float*)d_in[18];
    float* out = (float*)d_out;

    attr_kernel<<<8, 256>>>(attr_emb, Wt1, bt1, Wt2, bt2);
    zero_attlog_kernel<<<(NCOL + 255) / 256, 256>>>();
    conv_att_kernel<<<dim3(NCOL / 128, CMID / 128), 256>>>(
        x, Wc, bc, bn_gamma, bn_beta, bn_mean, bn_var, c);
    softmax_kernel<<<BATCH, 256>>>();
    feat_kernel<<<BATCH, 256>>>(x);
    // H1 = relu([feat | attr2] @ W1^T + b1) : M=512, N=512, K=1536
    gemm64_kernel<1, 1, 0><<<dim3(512 / 64, BATCH / 64), 256>>>(W1, b1, nullptr, 512, 1536, c);
    // mask = sigmoid(H1 @ W2^T + b2) : M=512, N=1024, K=512
    gemm64_kernel<0, 2, 1><<<dim3(1024 / 64, BATCH / 64), 256>>>(W2, b2, nullptr, 1024, 512, c);
    // out = (feat*mask) @ Wf^T + bf : M=512, N=1024, K=1024
    gemm64_kernel<2, 0, 2><<<dim3(1024 / 64, BATCH / 64), 256>>>(Wf, bf, out, 1024, 1024, c);
    l2norm_kernel<<<BATCH, 256>>>(out);
}

// round 4
// speedup vs baseline: 1.6612x; 1.6612x over previous
#include <cuda_runtime.h>
#include <cuda_bf16.h>
#include <math.h>
#include <stdint.h>

#define BATCH 512
#define CIN   1024
#define CMID  512
#define HW2   196
#define EMBD  1024
#define NCOL  (BATCH * HW2)   // 100352 = 1568 * 64

// ---------------- scratch (device globals; no allocations allowed) ----------
__device__ float g_attr1[8 * 512];
__device__ float g_attr2[8 * 512];
__device__ float g_attlog[NCOL];
__device__ float g_attp[NCOL];
__device__ float g_feat[BATCH * 1024];
__device__ float g_h1[BATCH * 512];
__device__ float g_mask[BATCH * 1024];
__device__ float g_bi[CMID];
__device__ __align__(16) __nv_bfloat16 g_Wc_hi[CMID * CIN];
__device__ __align__(16) __nv_bfloat16 g_Wc_lo[CMID * CIN];
// x transposed to [K][N] and split hi/lo (205 MB each)
__device__ __align__(16) __nv_bfloat16 g_xh[(size_t)CIN * NCOL];
__device__ __align__(16) __nv_bfloat16 g_xl[(size_t)CIN * NCOL];

// ======================= PTX helpers (non-'a' features only) ================
__device__ __forceinline__ uint32_t smem_u32(const void* p) {
    uint32_t a;
    asm("{ .reg .u64 t; cvta.to.shared.u64 t, %1; cvt.u32.u64 %0, t; }" : "=r"(a) : "l"(p));
    return a;
}
#define CP_ASYNC16(dst, src) \
    asm volatile("cp.async.cg.shared.global [%0], [%1], 16;" :: "r"(dst), "l"(src) : "memory")
#define CP_COMMIT() asm volatile("cp.async.commit_group;" ::: "memory")
#define CP_WAIT(n)  asm volatile("cp.async.wait_group %0;" :: "n"(n) : "memory")

#define LDSM_X4(r0, r1, r2, r3, addr) \
    asm volatile("ldmatrix.sync.aligned.m8n8.x4.shared.b16 {%0,%1,%2,%3}, [%4];" \
                 : "=r"(r0), "=r"(r1), "=r"(r2), "=r"(r3) : "r"(addr))
#define LDSM_X4T(r0, r1, r2, r3, addr) \
    asm volatile("ldmatrix.sync.aligned.m8n8.x4.trans.shared.b16 {%0,%1,%2,%3}, [%4];" \
                 : "=r"(r0), "=r"(r1), "=r"(r2), "=r"(r3) : "r"(addr))

#define MMA16816(C, A, B0, B1) \
    asm volatile("mma.sync.aligned.m16n8k16.row.col.f32.bf16.bf16.f32 " \
                 "{%0,%1,%2,%3},{%4,%5,%6,%7},{%8,%9},{%0,%1,%2,%3};" \
                 : "+f"((C)[0]), "+f"((C)[1]), "+f"((C)[2]), "+f"((C)[3]) \
                 : "r"((A)[0]), "r"((A)[1]), "r"((A)[2]), "r"((A)[3]), "r"(B0), "r"(B1))

__device__ __forceinline__ float ftanh(float x) {
    x = fminf(fmaxf(x, -12.f), 12.f);
    float e = __expf(2.f * x);
    return __fdividef(e - 1.f, e + 1.f);
}

// ======================= prep: fold BN scale into Wc, split bf16 ============
__global__ void wc_prep_kernel(const float* __restrict__ Wc, const float* __restrict__ bc,
                               const float* __restrict__ gamma, const float* __restrict__ beta,
                               const float* __restrict__ mean, const float* __restrict__ var) {
    int o = blockIdx.x, tid = threadIdx.x;  // 256 threads, 4 elems each
    float sc = gamma[o] * rsqrtf(var[o] + 1e-5f);
    if (tid == 0) g_bi[o] = (bc[o] - mean[o]) * sc + beta[o];
    float4 v = ((const float4*)(Wc + (size_t)o * CIN))[tid];
    v.x *= sc; v.y *= sc; v.z *= sc; v.w *= sc;
    __nv_bfloat16 h0 = __float2bfloat16_rn(v.x), h1 = __float2bfloat16_rn(v.y);
    __nv_bfloat16 h2 = __float2bfloat16_rn(v.z), h3 = __float2bfloat16_rn(v.w);
    __nv_bfloat16 l0 = __float2bfloat16_rn(v.x - __bfloat162float(h0));
    __nv_bfloat16 l1 = __float2bfloat16_rn(v.y - __bfloat162float(h1));
    __nv_bfloat16 l2 = __float2bfloat16_rn(v.z - __bfloat162float(h2));
    __nv_bfloat16 l3 = __float2bfloat16_rn(v.w - __bfloat162float(h3));
    uint2 uh, ul;
    uh.x = (uint32_t)__bfloat16_as_ushort(h0) | ((uint32_t)__bfloat16_as_ushort(h1) << 16);
    uh.y = (uint32_t)__bfloat16_as_ushort(h2) | ((uint32_t)__bfloat16_as_ushort(h3) << 16);
    ul.x = (uint32_t)__bfloat16_as_ushort(l0) | ((uint32_t)__bfloat16_as_ushort(l1) << 16);
    ul.y = (uint32_t)__bfloat16_as_ushort(l2) | ((uint32_t)__bfloat16_as_ushort(l3) << 16);
    ((uint2*)g_Wc_hi)[o * 256 + tid] = uh;
    ((uint2*)g_Wc_lo)[o * 256 + tid] = ul;
}

// ======================= prep: transpose + split x to [K][N] bf16 ===========
__global__ void x_prep_kernel(const float* __restrict__ x) {
    int gw = blockIdx.x * 8 + (threadIdx.x >> 5);   // (b,k) row id
    int b = gw >> 10, k = gw & 1023;
    int lane = threadIdx.x & 31;
    const float* src = x + ((size_t)b * CIN + k) * HW2;
    size_t dst = (size_t)k * NCOL + (size_t)b * HW2;
    #pragma unroll
    for (int i = lane; i < HW2; i += 32) {
        float v = src[i];
        __nv_bfloat16 h = __float2bfloat16_rn(v);
        __nv_bfloat16 l = __float2bfloat16_rn(v - __bfloat162float(h));
        g_xh[dst + i] = h;
        g_xl[dst + i] = l;
    }
}

// ---------------- attr tables: 8 x 512, tiny -------------------------------
__global__ void attr_kernel(const float* __restrict__ emb,
                            const float* __restrict__ Wt1, const float* __restrict__ bt1,
                            const float* __restrict__ Wt2, const float* __restrict__ bt2) {
    int a = blockIdx.x;
    __shared__ float e[512];
    int tid = threadIdx.x;
    e[tid]       = emb[a * 512 + tid];
    e[tid + 256] = emb[a * 512 + tid + 256];
    __syncthreads();
    int warp = tid >> 5, lane = tid & 31;
    for (int o = warp; o < 512; o += 8) {
        float s1 = 0.f, s2 = 0.f;
        for (int k = lane; k < 512; k += 32) {
            float ev = e[k];
            s1 = fmaf(ev, Wt1[o * 512 + k], s1);
            s2 = fmaf(ev, Wt2[o * 512 + k], s2);
        }
        #pragma unroll
        for (int off = 16; off; off >>= 1) {
            s1 += __shfl_down_sync(0xffffffffu, s1, off);
            s2 += __shfl_down_sync(0xffffffffu, s2, off);
        }
        if (lane == 0) {
            g_attr1[a * 512 + o] = tanhf(s1 + bt1[o]);
            g_attr2[a * 512 + o] = fmaxf(s2 + bt2[o], 0.f);
        }
    }
}

__global__ void zero_attlog_kernel() {
    int i = blockIdx.x * blockDim.x + threadIdx.x;
    if (i < NCOL) g_attlog[i] = 0.f;
}

// ======================= HMMA fused conv+BN+tanh+attn dot ===================
// GEMM M=512(o) x N=100352 x K=1024, bf16 3-way split on tensor cores.
// Grid (1568, 2): blockIdx.x = 64-col N tile, blockIdx.y = 256-row M half.
// CTA: 8 warps as 2(m) x 4(n); warp tile 128M x 16N; K chunk 32, double buffer.
// smem stage: Ah[256x80B] Al[256x80B] Bh[32x144B] Bl[32x144B] = 50176 B.
#define ST_A   20480
#define ST_B   4608
#define ST_BYTES (2 * ST_A + 2 * ST_B)   // 50176
#define CONV_SMEM (2 * ST_BYTES)         // 100352

__global__ void __launch_bounds__(256, 2) conv_att_hmma(const int* __restrict__ cidx) {
    extern __shared__ char smem[];
    uint32_t sb = smem_u32(smem);
    int tid = threadIdx.x, wid = tid >> 5, lane = tid & 31;
    int wn = wid & 3, wm = wid >> 2;
    int n0 = blockIdx.x * 64;
    int m0 = blockIdx.y * 256;

    // ---- per-thread cp.async source/dest precompute ----
    // A: 8 chunks of 16B (t<4: hi, t>=4: lo)
    const __nv_bfloat16* a_src[8];
    uint32_t a_dst[8];
    #pragma unroll
    for (int t = 0; t < 8; t++) {
        int i = t * 256 + tid;
        int prec = i >> 10, c = i & 1023;
        int row = c >> 2, ch = c & 3;
        a_src[t] = (prec ? g_Wc_lo : g_Wc_hi) + (size_t)(m0 + row) * CIN + ch * 8;
        a_dst[t] = sb + prec * ST_A + row * 80 + ch * 16;
    }
    // B: 2 chunks of 16B
    const __nv_bfloat16* b_src[2];
    uint32_t b_dst[2];
    #pragma unroll
    for (int t = 0; t < 2; t++) {
        int i = t * 256 + tid;
        int prec = i >> 8, c = i & 255;
        int row = c >> 3, ch = c & 7;
        b_src[t] = (prec ? g_xl : g_xh) + (size_t)row * NCOL + n0 + ch * 8;
        b_dst[t] = sb + 2 * ST_A + prec * ST_B + row * 144 + ch * 16;
    }

    float acc[8][2][4];
    #pragma unroll
    for (int mi = 0; mi < 8; mi++)
        #pragma unroll
        for (int nj = 0; nj < 2; nj++)
            #pragma unroll
            for (int r = 0; r < 4; r++) acc[mi][nj][r] = 0.f;

    // ldmatrix base offsets (per buffer added later)
    // A: row = wm*128 + mi*16 + (lane&15); byte = row*80 + kstep*32 + ((lane>>4)&1)*16
    uint32_t a_lds = sb + (uint32_t)(wm * 128 + (lane & 15)) * 80 + ((lane >> 4) & 1) * 16;
    // B: row k = kstep*16 + (lane&15); col = wn*16 + ((lane>>4)&1)*8
    uint32_t b_lds = sb + 2 * ST_A + (uint32_t)(lane & 15) * 144 +
                     (uint32_t)(wn * 16 + ((lane >> 4) & 1) * 8) * 2;

    // ---- prologue: stage 0 ----
    #pragma unroll
    for (int t = 0; t < 8; t++) CP_ASYNC16(a_dst[t], a_src[t]);
    #pragma unroll
    for (int t = 0; t < 2; t++) CP_ASYNC16(b_dst[t], b_src[t]);
    CP_COMMIT();

    for (int s = 0; s < 32; s++) {
        uint32_t nbuf = ((s + 1) & 1) * ST_BYTES;
        if (s < 31) {
            size_t ka = (size_t)(s + 1) * 32;              // k offset for A (elems)
            size_t kb = (size_t)(s + 1) * 32 * NCOL;       // k offset for B (elems)
            #pragma unroll
            for (int t = 0; t < 8; t++) CP_ASYNC16(a_dst[t] + nbuf, a_src[t] + ka);
            #pragma unroll
            for (int t = 0; t < 2; t++) CP_ASYNC16(b_dst[t] + nbuf, b_src[t] + kb);
            CP_COMMIT();
            CP_WAIT(1);
        } else {
            CP_WAIT(0);
        }
        __syncthreads();

        uint32_t cbuf = (s & 1) * ST_BYTES;
        #pragma unroll
        for (int ks = 0; ks < 2; ks++) {
            uint32_t bh[4], bl[4];
            uint32_t baddr = b_lds + cbuf + (uint32_t)(ks * 16) * 144;
            LDSM_X4T(bh[0], bh[1], bh[2], bh[3], baddr);
            LDSM_X4T(bl[0], bl[1], bl[2], bl[3], baddr + ST_B);
            #pragma unroll
            for (int mi = 0; mi < 8; mi++) {
                uint32_t ah[4], al[4];
                uint32_t aaddr = a_lds + cbuf + (uint32_t)(mi * 16) * 80 + ks * 32;
                LDSM_X4(ah[0], ah[1], ah[2], ah[3], aaddr);
                LDSM_X4(al[0], al[1], al[2], al[3], aaddr + ST_A);
                MMA16816(acc[mi][0], ah, bh[0], bh[1]);
                MMA16816(acc[mi][1], ah, bh[2], bh[3]);
                MMA16816(acc[mi][0], ah, bl[0], bl[1]);
                MMA16816(acc[mi][1], ah, bl[2], bl[3]);
                MMA16816(acc[mi][0], al, bh[0], bh[1]);
                MMA16816(acc[mi][1], al, bh[2], bh[3]);
            }
        }
        __syncthreads();
    }

    // ---- epilogue: logits[n] += sum_m attr1[c(n)][m] * tanh(D[m][n]+bi[m]) ----
    int b0 = n0 / HW2;
    int ncut = (b0 + 1) * HW2;                 // first col of next batch
    int b1 = (ncut < n0 + 64) ? b0 + 1 : b0;
    int c0i = cidx[b0], c1i = cidx[b1];
    int r0 = lane >> 2;
    int colE = (lane & 3) * 2;

    float accE[2] = {0.f, 0.f}, accO[2] = {0.f, 0.f};
    #pragma unroll
    for (int mi = 0; mi < 8; mi++) {
        int mA = m0 + wm * 128 + mi * 16 + r0;
        int mB = mA + 8;
        float biA = g_bi[mA], biB = g_bi[mB];
        float a0A = g_attr1[c0i * 512 + mA], a1A = g_attr1[c1i * 512 + mA];
        float a0B = g_attr1[c0i * 512 + mB], a1B = g_attr1[c1i * 512 + mB];
        #pragma unroll
        for (int nj = 0; nj < 2; nj++) {
            int colg = n0 + wn * 16 + nj * 8 + colE;
            float awAe = (colg < ncut) ? a0A : a1A;
            float awBe = (colg < ncut) ? a0B : a1B;
            float awAo = (colg + 1 < ncut) ? a0A : a1A;
            float awBo = (colg + 1 < ncut) ? a0B : a1B;
            accE[nj] += awAe * ftanh(acc[mi][nj][0] + biA) + awBe * ftanh(acc[mi][nj][2] + biB);
            accO[nj] += awAo * ftanh(acc[mi][nj][1] + biA) + awBo * ftanh(acc[mi][nj][3] + biB);
        }
    }
    // reduce over lanes with same (lane&3): xor over bits 2..4
    #pragma unroll
    for (int off = 4; off <= 16; off <<= 1) {
        #pragma unroll
        for (int nj = 0; nj < 2; nj++) {
            accE[nj] += __shfl_xor_sync(0xffffffffu, accE[nj], off);
            accO[nj] += __shfl_xor_sync(0xffffffffu, accO[nj], off);
        }
    }
    __syncthreads();                      // smem reuse safe
    float* sred = (float*)smem;           // [8 warps][16 cols]
    if (lane < 4) {
        #pragma unroll
        for (int nj = 0; nj < 2; nj++) {
            sred[wid * 16 + nj * 8 + lane * 2]     = accE[nj];
            sred[wid * 16 + nj * 8 + lane * 2 + 1] = accO[nj];
        }
    }
    __syncthreads();
    if (tid < 64) {
        int wnf = tid >> 4, cl = tid & 15;
        float t = sred[wnf * 16 + cl] + sred[(wnf + 4) * 16 + cl];
        atomicAdd(&g_attlog[n0 + tid], t);
    }
}

// ---------------- spatial softmax per batch --------------------------------
__global__ void softmax_kernel() {
    int b = blockIdx.x, tid = threadIdx.x;
    __shared__ float sh[256];
    float v = (tid < HW2) ? g_attlog[b * HW2 + tid] * 0.044194173824159216f : -1e30f;
    sh[tid] = v;
    __syncthreads();
    for (int s = 128; s; s >>= 1) {
        if (tid < s) sh[tid] = fmaxf(sh[tid], sh[tid + s]);
        __syncthreads();
    }
    float mx = sh[0];
    __syncthreads();
    float e = (tid < HW2) ? expf(v - mx) : 0.f;
    sh[tid] = e;
    __syncthreads();
    for (int s = 128; s; s >>= 1) {
        if (tid < s) sh[tid] += sh[tid + s];
        __syncthreads();
    }
    float inv = 1.f / sh[0];
    if (tid < HW2) g_attp[b * HW2 + tid] = e * inv;
}

// ---------------- feat[b,c] = sum_hw x[b,c,hw] * p[b,hw] -------------------
__global__ void feat_kernel(const float* __restrict__ x) {
    int b = blockIdx.x;
    __shared__ float p[HW2];
    int tid = threadIdx.x;
    if (tid < HW2) p[tid] = g_attp[b * HW2 + tid];
    __syncthreads();
    int warp = tid >> 5, lane = tid & 31;
    const float* xb = x + (size_t)b * (CIN * HW2);
    for (int cch = warp; cch < CIN; cch += 8) {
        float sum = 0.f;
        for (int hw = lane; hw < HW2; hw += 32)
            sum = fmaf(xb[cch * HW2 + hw], p[hw], sum);
        #pragma unroll
        for (int off = 16; off; off >>= 1)
            sum += __shfl_down_sync(0xffffffffu, sum, off);
        if (lane == 0) g_feat[b * CIN + cch] = sum;
    }
}

// ---------------- generic 64x64 GEMM: C = act(A @ W^T + bias) --------------
template <int MODE, int ACT, int DST>
__global__ void __launch_bounds__(256) gemm64_kernel(
    const float* __restrict__ W, const float* __restrict__ bias,
    float* __restrict__ Cout, int N, int K, const int* __restrict__ cidx) {
    __shared__ float As[16][64];
    __shared__ float Ws[16][64];
    int tid = threadIdx.x;
    int n0 = blockIdx.x * 64, m0 = blockIdx.y * 64;
    int lr = tid >> 2;
    int lk = (tid & 3) << 2;
    int tm = tid >> 4, tn = tid & 15;

    float acc[4][4];
    #pragma unroll
    for (int i = 0; i < 4; i++)
        #pragma unroll
        for (int j = 0; j < 4; j++) acc[i][j] = 0.f;

    for (int k0 = 0; k0 < K; k0 += 16) {
        int m = m0 + lr, k = k0 + lk;
        float4 av;
        if (MODE == 0) {
            av = *(const float4*)(g_h1 + (size_t)m * 512 + k);
        } else if (MODE == 1) {
            if (k < 1024) av = *(const float4*)(g_feat + (size_t)m * 1024 + k);
            else          av = *(const float4*)(g_attr2 + cidx[m] * 512 + (k - 1024));
        } else {
            float4 f = *(const float4*)(g_feat + (size_t)m * 1024 + k);
            float4 g = *(const float4*)(g_mask + (size_t)m * 1024 + k);
            av = make_float4(f.x * g.x, f.y * g.y, f.z * g.z, f.w * g.w);
        }
        As[lk + 0][lr] = av.x; As[lk + 1][lr] = av.y;
        As[lk + 2][lr] = av.z; As[lk + 3][lr] = av.w;

        float4 wv = *(const float4*)(W + (size_t)(n0 + lr) * K + k);
        Ws[lk + 0][lr] = wv.x; Ws[lk + 1][lr] = wv.y;
        Ws[lk + 2][lr] = wv.z; Ws[lk + 3][lr] = wv.w;
        __syncthreads();
        #pragma unroll
        for (int kk = 0; kk < 16; kk++) {
            float a[4], b[4];
            *(float4*)a = *(const float4*)&As[kk][tm * 4];
            *(float4*)b = *(const float4*)&Ws[kk][tn * 4];
            #pragma unroll
            for (int i = 0; i < 4; i++)
                #pragma unroll
                for (int j = 0; j < 4; j++)
                    acc[i][j] = fmaf(a[i], b[j], acc[i][j]);
        }
        __syncthreads();
    }

    float* Cp = (DST == 0) ? g_h1 : (DST == 1) ? g_mask : Cout;
    #pragma unroll
    for (int j = 0; j < 4; j++) {
        int n = n0 + tn * 4 + j;
        float bv = bias[n];
        #pragma unroll
        for (int i = 0; i < 4; i++) {
            int m = m0 + tm * 4 + i;
            float v = acc[i][j] + bv;
            if (ACT == 1) v = fmaxf(v, 0.f);
            else if (ACT == 2) v = 1.f / (1.f + expf(-v));
            Cp[(size_t)m * N + n] = v;
        }
    }
}

// ---------------- row-wise L2 normalize in place ----------------------------
__global__ void l2norm_kernel(float* __restrict__ out) {
    int b = blockIdx.x, tid = threadIdx.x;
    __shared__ float sh[256];
    float s = 0.f;
    for (int i = tid; i < EMBD; i += 256) {
        float v = out[(size_t)b * EMBD + i];
        s = fmaf(v, v, s);
    }
    sh[tid] = s;
    __syncthreads();
    for (int st = 128; st; st >>= 1) {
        if (tid < st) sh[tid] += sh[tid + st];
        __syncthreads();
    }
    float inv = 1.f / sqrtf(sh[0]);
    for (int i = tid; i < EMBD; i += 256) out[(size_t)b * EMBD + i] *= inv;
}

// ---------------- launch ----------------------------------------------------
extern "C" void kernel_launch(void* const* d_in, const int* in_sizes, int n_in,
                              void* d_out, int out_size) {
    const float* x        = (const float*)d_in[0];
    const int*   c        = (const int*)  d_in[1];
    const float* attr_emb = (const float*)d_in[2];
    const float* Wt1      = (const float*)d_in[3];
    const float* bt1      = (const float*)d_in[4];
    const float* Wc       = (const float*)d_in[5];
    const float* bc       = (const float*)d_in[6];
    const float* bn_gamma = (const float*)d_in[7];
    const float* bn_beta  = (const float*)d_in[8];
    const float* bn_mean  = (const float*)d_in[9];
    const float* bn_var   = (const float*)d_in[10];
    const float* Wt2      = (const float*)d_in[11];
    const float* bt2      = (const float*)d_in[12];
    const float* W1       = (const float*)d_in[13];
    const float* b1       = (const float*)d_in[14];
    const float* W2       = (const float*)d_in[15];
    const float* b2       = (const float*)d_in[16];
    const float* Wf       = (const float*)d_in[17];
    const float* bf       = (const float*)d_in[18];
    float* out = (float*)d_out;

    static bool attr_set = false;
    if (!attr_set) {
        cudaFuncSetAttribute(conv_att_hmma, cudaFuncAttributeMaxDynamicSharedMemorySize, CONV_SMEM);
        attr_set = true;
    }

    wc_prep_kernel<<<CMID, 256>>>(Wc, bc, bn_gamma, bn_beta, bn_mean, bn_var);
    x_prep_kernel<<<BATCH * CIN / 8, 256>>>(x);
    attr_kernel<<<8, 256>>>(attr_emb, Wt1, bt1, Wt2, bt2);
    zero_attlog_kernel<<<(NCOL + 255) / 256, 256>>>();
    conv_att_hmma<<<dim3(NCOL / 64, 2), 256, CONV_SMEM>>>(c);
    softmax_kernel<<<BATCH, 256>>>();
    feat_kernel<<<BATCH, 256>>>(x);
    gemm64_kernel<1, 1, 0><<<dim3(512 / 64, BATCH / 64), 256>>>(W1, b1, nullptr, 512, 1536, c);
    gemm64_kernel<0, 2, 1><<<dim3(1024 / 64, BATCH / 64), 256>>>(W2, b2, nullptr, 1024, 512, c);
    gemm64_kernel<2, 0, 2><<<dim3(1024 / 64, BATCH / 64), 256>>>(Wf, bf, out, 1024, 1024, c);
    l2norm_kernel<<<BATCH, 256>>>(out);
}

// round 5
// speedup vs baseline: 2.0688x; 1.2454x over previous
#include <cuda_runtime.h>
#include <cuda_fp16.h>
#include <math.h>
#include <stdint.h>

#define BATCH 512
#define CIN   1024
#define CMID  512
#define HW2   196
#define EMBD  1024
#define NCOL  (BATCH * HW2)   // 100352 = 1568 * 64

// ---------------- scratch (device globals; no allocations allowed) ----------
__device__ float g_attr1[8 * 512];
__device__ float g_attr2[8 * 512];
__device__ float g_attlog[NCOL];
__device__ float g_attp[NCOL];
__device__ float g_feat[BATCH * 1024];
__device__ float g_h1[BATCH * 512];
__device__ float g_mask[BATCH * 1024];
__device__ float g_bi[CMID];
__device__ __align__(16) __half g_Wc_hi[CMID * CIN];
__device__ __align__(16) __half g_Wc_lo[CMID * CIN];
// x transposed to [K][N] fp16 (205 MB)
__device__ __align__(16) __half g_xh[(size_t)CIN * NCOL];

// ======================= PTX helpers (non-'a' features only) ================
__device__ __forceinline__ uint32_t smem_u32(const void* p) {
    uint32_t a;
    asm("{ .reg .u64 t; cvta.to.shared.u64 t, %1; cvt.u32.u64 %0, t; }" : "=r"(a) : "l"(p));
    return a;
}
#define CP_ASYNC16(dst, src) \
    asm volatile("cp.async.cg.shared.global [%0], [%1], 16;" :: "r"(dst), "l"(src) : "memory")
#define CP_COMMIT() asm volatile("cp.async.commit_group;" ::: "memory")
#define CP_WAIT(n)  asm volatile("cp.async.wait_group %0;" :: "n"(n) : "memory")

#define LDSM_X4(r0, r1, r2, r3, addr) \
    asm volatile("ldmatrix.sync.aligned.m8n8.x4.shared.b16 {%0,%1,%2,%3}, [%4];" \
                 : "=r"(r0), "=r"(r1), "=r"(r2), "=r"(r3) : "r"(addr))
#define LDSM_X4T(r0, r1, r2, r3, addr) \
    asm volatile("ldmatrix.sync.aligned.m8n8.x4.trans.shared.b16 {%0,%1,%2,%3}, [%4];" \
                 : "=r"(r0), "=r"(r1), "=r"(r2), "=r"(r3) : "r"(addr))

#define MMA16816(C, A, B0, B1) \
    asm volatile("mma.sync.aligned.m16n8k16.row.col.f32.f16.f16.f32 " \
                 "{%0,%1,%2,%3},{%4,%5,%6,%7},{%8,%9},{%0,%1,%2,%3};" \
                 : "+f"((C)[0]), "+f"((C)[1]), "+f"((C)[2]), "+f"((C)[3]) \
                 : "r"((A)[0]), "r"((A)[1]), "r"((A)[2]), "r"((A)[3]), "r"(B0), "r"(B1))

__device__ __forceinline__ float ftanh(float x) {
    x = fminf(fmaxf(x, -12.f), 12.f);
    float e = __expf(2.f * x);
    return __fdividef(e - 1.f, e + 1.f);
}

// ====== prep 1: fold BN scale into Wc, split fp16; ALSO zero g_attlog =======
__global__ void wc_prep_kernel(const float* __restrict__ Wc, const float* __restrict__ bc,
                               const float* __restrict__ gamma, const float* __restrict__ beta,
                               const float* __restrict__ mean, const float* __restrict__ var) {
    int o = blockIdx.x, tid = threadIdx.x;  // 512 blocks x 256 threads
    int zi = o * 256 + tid;
    if (zi < NCOL) g_attlog[zi] = 0.f;
    float sc = gamma[o] * rsqrtf(var[o] + 1e-5f);
    if (tid == 0) g_bi[o] = (bc[o] - mean[o]) * sc + beta[o];
    float4 v = ((const float4*)(Wc + (size_t)o * CIN))[tid];
    v.x *= sc; v.y *= sc; v.z *= sc; v.w *= sc;
    __half h0 = __float2half_rn(v.x), h1 = __float2half_rn(v.y);
    __half h2 = __float2half_rn(v.z), h3 = __float2half_rn(v.w);
    __half l0 = __float2half_rn(v.x - __half2float(h0));
    __half l1 = __float2half_rn(v.y - __half2float(h1));
    __half l2 = __float2half_rn(v.z - __half2float(h2));
    __half l3 = __float2half_rn(v.w - __half2float(h3));
    uint2 uh, ul;
    uh.x = (uint32_t)__half_as_ushort(h0) | ((uint32_t)__half_as_ushort(h1) << 16);
    uh.y = (uint32_t)__half_as_ushort(h2) | ((uint32_t)__half_as_ushort(h3) << 16);
    ul.x = (uint32_t)__half_as_ushort(l0) | ((uint32_t)__half_as_ushort(l1) << 16);
    ul.y = (uint32_t)__half_as_ushort(l2) | ((uint32_t)__half_as_ushort(l3) << 16);
    ((uint2*)g_Wc_hi)[o * 256 + tid] = uh;
    ((uint2*)g_Wc_lo)[o * 256 + tid] = ul;
}

// ====== prep 2: transpose x to [K][N] fp16 ==================================
__global__ void x_prep_kernel(const float* __restrict__ x) {
    int gw = blockIdx.x * 8 + (threadIdx.x >> 5);   // (b,k) row id
    int b = gw >> 10, k = gw & 1023;
    int lane = threadIdx.x & 31;
    const float* src = x + ((size_t)b * CIN + k) * HW2;
    size_t dst = (size_t)k * NCOL + (size_t)b * HW2;
    #pragma unroll
    for (int i = lane; i < HW2; i += 32)
        g_xh[dst + i] = __float2half_rn(src[i]);
}

// ---------------- attr tables: 8 x 512, tiny -------------------------------
__global__ void attr_kernel(const float* __restrict__ emb,
                            const float* __restrict__ Wt1, const float* __restrict__ bt1,
                            const float* __restrict__ Wt2, const float* __restrict__ bt2) {
    int a = blockIdx.x;
    __shared__ float e[512];
    int tid = threadIdx.x;
    e[tid]       = emb[a * 512 + tid];
    e[tid + 256] = emb[a * 512 + tid + 256];
    __syncthreads();
    int warp = tid >> 5, lane = tid & 31;
    for (int o = warp; o < 512; o += 8) {
        float s1 = 0.f, s2 = 0.f;
        for (int k = lane; k < 512; k += 32) {
            float ev = e[k];
            s1 = fmaf(ev, Wt1[o * 512 + k], s1);
            s2 = fmaf(ev, Wt2[o * 512 + k], s2);
        }
        #pragma unroll
        for (int off = 16; off; off >>= 1) {
            s1 += __shfl_down_sync(0xffffffffu, s1, off);
            s2 += __shfl_down_sync(0xffffffffu, s2, off);
        }
        if (lane == 0) {
            g_attr1[a * 512 + o] = tanhf(s1 + bt1[o]);
            g_attr2[a * 512 + o] = fmaxf(s2 + bt2[o], 0.f);
        }
    }
}

// ======================= HMMA fused conv+BN+tanh+attn dot ===================
// GEMM M=512(o) x N=100352 x K=1024, fp16 2-product split on tensor cores.
// Grid (1568, 2): blockIdx.x = 64-col N tile, blockIdx.y = 256-row M half.
// CTA: 8 warps as 4(m) x 2(n); warp tile 64M x 32N; K chunk 32, double buffer.
// smem stage: Ah[256x80B] Al[256x80B] B[32x144B] = 45568 B.
#define ST_A   20480
#define ST_B   4608
#define ST_BYTES (2 * ST_A + ST_B)   // 45568
#define CONV_SMEM (2 * ST_BYTES)     // 91136

__global__ void __launch_bounds__(256, 2) conv_att_hmma(const int* __restrict__ cidx) {
    extern __shared__ char smem[];
    uint32_t sb = smem_u32(smem);
    int tid = threadIdx.x, wid = tid >> 5, lane = tid & 31;
    int wm = wid & 3, wn = wid >> 2;
    int n0 = blockIdx.x * 64;
    int m0 = blockIdx.y * 256;

    // ---- cp.async offsets: A has 4 offset patterns reused for hi/lo ----
    uint32_t a_soff[4], a_doff[4];
    #pragma unroll
    for (int t = 0; t < 4; t++) {
        int i = t * 256 + tid;          // 0..1023
        int row = i >> 2, ch = i & 3;
        a_soff[t] = (uint32_t)((m0 + row) * CIN + ch * 8);
        a_doff[t] = (uint32_t)(row * 80 + ch * 16);
    }
    int bkrow = tid >> 3, bch = tid & 7;
    uint32_t b_soff = (uint32_t)bkrow * NCOL + (uint32_t)(n0 + bch * 8);
    uint32_t b_doff = 2 * ST_A + (uint32_t)(bkrow * 144 + bch * 16);

    float acc[4][4][4];
    #pragma unroll
    for (int mi = 0; mi < 4; mi++)
        #pragma unroll
        for (int nj = 0; nj < 4; nj++)
            #pragma unroll
            for (int r = 0; r < 4; r++) acc[mi][nj][r] = 0.f;

    // ldmatrix bases
    uint32_t a_lds = sb + (uint32_t)(wm * 64 + (lane & 15)) * 80 + ((lane >> 4) & 1) * 16;
    uint32_t b_lds = sb + 2 * ST_A + (uint32_t)(lane & 15) * 144 +
                     (uint32_t)(wn * 32 + ((lane >> 4) & 1) * 8) * 2;

    // ---- prologue: stage 0 ----
    #pragma unroll
    for (int t = 0; t < 4; t++) {
        CP_ASYNC16(sb + a_doff[t], g_Wc_hi + a_soff[t]);
        CP_ASYNC16(sb + ST_A + a_doff[t], g_Wc_lo + a_soff[t]);
    }
    CP_ASYNC16(sb + b_doff, g_xh + b_soff);
    CP_COMMIT();

    for (int s = 0; s < 32; s++) {
        uint32_t nbuf = ((s + 1) & 1) * ST_BYTES;
        if (s < 31) {
            uint32_t ka = (uint32_t)(s + 1) * 32;
            size_t kb = (size_t)(s + 1) * 32 * NCOL;
            #pragma unroll
            for (int t = 0; t < 4; t++) {
                CP_ASYNC16(sb + a_doff[t] + nbuf, g_Wc_hi + a_soff[t] + ka);
                CP_ASYNC16(sb + ST_A + a_doff[t] + nbuf, g_Wc_lo + a_soff[t] + ka);
            }
            CP_ASYNC16(sb + b_doff + nbuf, g_xh + b_soff + kb);
            CP_COMMIT();
            CP_WAIT(1);
        } else {
            CP_WAIT(0);
        }
        __syncthreads();

        uint32_t cbuf = (s & 1) * ST_BYTES;
        #pragma unroll
        for (int ks = 0; ks < 2; ks++) {
            uint32_t b0[4], b1[4];
            uint32_t baddr = b_lds + cbuf + (uint32_t)(ks * 16) * 144;
            LDSM_X4T(b0[0], b0[1], b0[2], b0[3], baddr);        // cols +0..15
            LDSM_X4T(b1[0], b1[1], b1[2], b1[3], baddr + 32);   // cols +16..31
            #pragma unroll
            for (int mi = 0; mi < 4; mi++) {
                uint32_t ah[4], al[4];
                uint32_t aaddr = a_lds + cbuf + (uint32_t)(mi * 16) * 80 + ks * 32;
                LDSM_X4(ah[0], ah[1], ah[2], ah[3], aaddr);
                LDSM_X4(al[0], al[1], al[2], al[3], aaddr + ST_A);
                MMA16816(acc[mi][0], ah, b0[0], b0[1]);
                MMA16816(acc[mi][1], ah, b0[2], b0[3]);
                MMA16816(acc[mi][2], ah, b1[0], b1[1]);
                MMA16816(acc[mi][3], ah, b1[2], b1[3]);
                MMA16816(acc[mi][0], al, b0[0], b0[1]);
                MMA16816(acc[mi][1], al, b0[2], b0[3]);
                MMA16816(acc[mi][2], al, b1[0], b1[1]);
                MMA16816(acc[mi][3], al, b1[2], b1[3]);
            }
        }
        __syncthreads();
    }

    // ---- epilogue: logits[n] += sum_m attr1[c(n)][m] * tanh(D[m][n]+bi[m]) ----
    int b0i = n0 / HW2;
    int ncut = (b0i + 1) * HW2;
    int b1i = (ncut < n0 + 64) ? b0i + 1 : b0i;
    int c0i = cidx[b0i], c1i = cidx[b1i];
    int r0 = lane >> 2;
    int colE = (lane & 3) * 2;

    float accE[4] = {0.f, 0.f, 0.f, 0.f}, accO[4] = {0.f, 0.f, 0.f, 0.f};
    #pragma unroll
    for (int mi = 0; mi < 4; mi++) {
        int mA = m0 + wm * 64 + mi * 16 + r0;
        int mB = mA + 8;
        float biA = g_bi[mA], biB = g_bi[mB];
        float a0A = g_attr1[c0i * 512 + mA], a1A = g_attr1[c1i * 512 + mA];
        float a0B = g_attr1[c0i * 512 + mB], a1B = g_attr1[c1i * 512 + mB];
        #pragma unroll
        for (int nj = 0; nj < 4; nj++) {
            int colg = n0 + wn * 32 + nj * 8 + colE;
            float awAe = (colg < ncut) ? a0A : a1A;
            float awBe = (colg < ncut) ? a0B : a1B;
            float awAo = (colg + 1 < ncut) ? a0A : a1A;
            float awBo = (colg + 1 < ncut) ? a0B : a1B;
            accE[nj] += awAe * ftanh(acc[mi][nj][0] + biA) + awBe * ftanh(acc[mi][nj][2] + biB);
            accO[nj] += awAo * ftanh(acc[mi][nj][1] + biA) + awBo * ftanh(acc[mi][nj][3] + biB);
        }
    }
    // reduce rows: lanes sharing (lane&3)
    #pragma unroll
    for (int off = 4; off <= 16; off <<= 1) {
        #pragma unroll
        for (int nj = 0; nj < 4; nj++) {
            accE[nj] += __shfl_xor_sync(0xffffffffu, accE[nj], off);
            accO[nj] += __shfl_xor_sync(0xffffffffu, accO[nj], off);
        }
    }
    __syncthreads();
    float* sred = (float*)smem;   // [8 warps][32 cols]
    if (lane < 4) {
        #pragma unroll
        for (int nj = 0; nj < 4; nj++) {
            sred[wid * 32 + nj * 8 + colE]     = accE[nj];
            sred[wid * 32 + nj * 8 + colE + 1] = accO[nj];
        }
    }
    __syncthreads();
    if (tid < 64) {
        int wnf = tid >> 5, cl = tid & 31;
        float t = 0.f;
        #pragma unroll
        for (int w = 0; w < 4; w++) t += sred[(wnf * 4 + w) * 32 + cl];
        atomicAdd(&g_attlog[n0 + tid], t);
    }
}

// ---------------- spatial softmax per batch --------------------------------
__global__ void softmax_kernel() {
    int b = blockIdx.x, tid = threadIdx.x;
    __shared__ float sh[256];
    float v = (tid < HW2) ? g_attlog[b * HW2 + tid] * 0.044194173824159216f : -1e30f;
    sh[tid] = v;
    __syncthreads();
    for (int s = 128; s; s >>= 1) {
        if (tid < s) sh[tid] = fmaxf(sh[tid], sh[tid + s]);
        __syncthreads();
    }
    float mx = sh[0];
    __syncthreads();
    float e = (tid < HW2) ? expf(v - mx) : 0.f;
    sh[tid] = e;
    __syncthreads();
    for (int s = 128; s; s >>= 1) {
        if (tid < s) sh[tid] += sh[tid + s];
        __syncthreads();
    }
    float inv = 1.f / sh[0];
    if (tid < HW2) g_attp[b * HW2 + tid] = e * inv;
}

// ---------------- feat[b,c] = sum_hw x[b,c,hw] * p[b,hw]  (fp16 x copy) -----
__global__ void feat_kernel() {
    int b = blockIdx.x;
    __shared__ float p[HW2];
    int tid = threadIdx.x;
    if (tid < HW2) p[tid] = g_attp[b * HW2 + tid];
    __syncthreads();
    int warp = tid >> 5, lane = tid & 31;
    const __half* xb = g_xh + (size_t)b * HW2;
    for (int k = warp; k < CIN; k += 8) {
        const __half* row = xb + (size_t)k * NCOL;
        float sum = 0.f;
        for (int hw = lane; hw < HW2; hw += 32)
            sum = fmaf(__half2float(row[hw]), p[hw], sum);
        #pragma unroll
        for (int off = 16; off; off >>= 1)
            sum += __shfl_down_sync(0xffffffffu, sum, off);
        if (lane == 0) g_feat[b * CIN + k] = sum;
    }
}

// ---------------- generic 64x64 GEMM: C = act(A @ W^T + bias) --------------
template <int MODE, int ACT, int DST>
__global__ void __launch_bounds__(256) gemm64_kernel(
    const float* __restrict__ W, const float* __restrict__ bias,
    float* __restrict__ Cout, int N, int K, const int* __restrict__ cidx) {
    __shared__ float As[16][64];
    __shared__ float Ws[16][64];
    int tid = threadIdx.x;
    int n0 = blockIdx.x * 64, m0 = blockIdx.y * 64;
    int lr = tid >> 2;
    int lk = (tid & 3) << 2;
    int tm = tid >> 4, tn = tid & 15;

    float acc[4][4];
    #pragma unroll
    for (int i = 0; i < 4; i++)
        #pragma unroll
        for (int j = 0; j < 4; j++) acc[i][j] = 0.f;

    for (int k0 = 0; k0 < K; k0 += 16) {
        int m = m0 + lr, k = k0 + lk;
        float4 av;
        if (MODE == 0) {
            av = *(const float4*)(g_h1 + (size_t)m * 512 + k);
        } else if (MODE == 1) {
            if (k < 1024) av = *(const float4*)(g_feat + (size_t)m * 1024 + k);
            else          av = *(const float4*)(g_attr2 + cidx[m] * 512 + (k - 1024));
        } else {
            float4 f = *(const float4*)(g_feat + (size_t)m * 1024 + k);
            float4 g = *(const float4*)(g_mask + (size_t)m * 1024 + k);
            av = make_float4(f.x * g.x, f.y * g.y, f.z * g.z, f.w * g.w);
        }
        As[lk + 0][lr] = av.x; As[lk + 1][lr] = av.y;
        As[lk + 2][lr] = av.z; As[lk + 3][lr] = av.w;

        float4 wv = *(const float4*)(W + (size_t)(n0 + lr) * K + k);
        Ws[lk + 0][lr] = wv.x; Ws[lk + 1][lr] = wv.y;
        Ws[lk + 2][lr] = wv.z; Ws[lk + 3][lr] = wv.w;
        __syncthreads();
        #pragma unroll
        for (int kk = 0; kk < 16; kk++) {
            float a[4], b[4];
            *(float4*)a = *(const float4*)&As[kk][tm * 4];
            *(float4*)b = *(const float4*)&Ws[kk][tn * 4];
            #pragma unroll
            for (int i = 0; i < 4; i++)
                #pragma unroll
                for (int j = 0; j < 4; j++)
                    acc[i][j] = fmaf(a[i], b[j], acc[i][j]);
        }
        __syncthreads();
    }

    float* Cp = (DST == 0) ? g_h1 : (DST == 1) ? g_mask : Cout;
    #pragma unroll
    for (int j = 0; j < 4; j++) {
        int n = n0 + tn * 4 + j;
        float bv = bias[n];
        #pragma unroll
        for (int i = 0; i < 4; i++) {
            int m = m0 + tm * 4 + i;
            float v = acc[i][j] + bv;
            if (ACT == 1) v = fmaxf(v, 0.f);
            else if (ACT == 2) v = 1.f / (1.f + expf(-v));
            Cp[(size_t)m * N + n] = v;
        }
    }
}

// ---------------- row-wise L2 normalize in place ----------------------------
__global__ void l2norm_kernel(float* __restrict__ out) {
    int b = blockIdx.x, tid = threadIdx.x;
    __shared__ float sh[256];
    float s = 0.f;
    for (int i = tid; i < EMBD; i += 256) {
        float v = out[(size_t)b * EMBD + i];
        s = fmaf(v, v, s);
    }
    sh[tid] = s;
    __syncthreads();
    for (int st = 128; st; st >>= 1) {
        if (tid < st) sh[tid] += sh[tid + st];
        __syncthreads();
    }
    float inv = 1.f / sqrtf(sh[0]);
    for (int i = tid; i < EMBD; i += 256) out[(size_t)b * EMBD + i] *= inv;
}

// ---------------- launch ----------------------------------------------------
extern "C" void kernel_launch(void* const* d_in, const int* in_sizes, int n_in,
                              void* d_out, int out_size) {
    const float* x        = (const float*)d_in[0];
    const int*   c        = (const int*)  d_in[1];
    const float* attr_emb = (const float*)d_in[2];
    const float* Wt1      = (const float*)d_in[3];
    const float* bt1      = (const float*)d_in[4];
    const float* Wc       = (const float*)d_in[5];
    const float* bc       = (const float*)d_in[6];
    const float* bn_gamma = (const float*)d_in[7];
    const float* bn_beta  = (const float*)d_in[8];
    const float* bn_mean  = (const float*)d_in[9];
    const float* bn_var   = (const float*)d_in[10];
    const float* Wt2      = (const float*)d_in[11];
    const float* bt2      = (const float*)d_in[12];
    const float* W1       = (const float*)d_in[13];
    const float* b1       = (const float*)d_in[14];
    const float* W2       = (const float*)d_in[15];
    const float* b2       = (const float*)d_in[16];
    const float* Wf       = (const float*)d_in[17];
    const float* bf       = (const float*)d_in[18];
    float* out = (float*)d_out;

    static bool attr_set = false;
    if (!attr_set) {
        cudaFuncSetAttribute(conv_att_hmma, cudaFuncAttributeMaxDynamicSharedMemorySize, CONV_SMEM);
        attr_set = true;
    }

    wc_prep_kernel<<<CMID, 256>>>(Wc, bc, bn_gamma, bn_beta, bn_mean, bn_var);  // also zeroes attlog
    x_prep_kernel<<<BATCH * CIN / 8, 256>>>(x);
    attr_kernel<<<8, 256>>>(attr_emb, Wt1, bt1, Wt2, bt2);
    conv_att_hmma<<<dim3(NCOL / 64, 2), 256, CONV_SMEM>>>(c);   // 4th launch -> ncu target
    softmax_kernel<<<BATCH, 256>>>();
    feat_kernel<<<BATCH, 256>>>();
    gemm64_kernel<1, 1, 0><<<dim3(512 / 64, BATCH / 64), 256>>>(W1, b1, nullptr, 512, 1536, c);
    gemm64_kernel<0, 2, 1><<<dim3(1024 / 64, BATCH / 64), 256>>>(W2, b2, nullptr, 1024, 512, c);
    gemm64_kernel<2, 0, 2><<<dim3(1024 / 64, BATCH / 64), 256>>>(Wf, bf, out, 1024, 1024, c);
    l2norm_kernel<<<BATCH, 256>>>(out);
}

// round 6
// speedup vs baseline: 2.5077x; 1.2122x over previous
#include <cuda_runtime.h>
#include <cuda_fp16.h>
#include <math.h>
#include <stdint.h>

#define BATCH 512
#define CIN   1024
#define CMID  512
#define HW2   196
#define EMBD  1024
#define NCOL  (BATCH * HW2)   // 100352 = 1568 * 64

// ---------------- scratch (device globals; no allocations allowed) ----------
__device__ float g_attr1[8 * 512];
__device__ float g_attr2[8 * 512];
__device__ float g_attlog[NCOL];
__device__ float g_attp[NCOL];
__device__ float g_feat[BATCH * 1024];
__device__ float g_h1[BATCH * 512];
__device__ float g_mask[BATCH * 1024];
__device__ float g_bi[CMID];
__device__ __align__(16) __half g_Wc_hi[CMID * CIN];
__device__ __align__(16) __half g_Wc_lo[CMID * CIN];
// x transposed to [K][N] fp16 (205 MB)
__device__ __align__(16) __half g_xh[(size_t)CIN * NCOL];

// ======================= PTX helpers (non-'a' features only) ================
__device__ __forceinline__ uint32_t smem_u32(const void* p) {
    uint32_t a;
    asm("{ .reg .u64 t; cvta.to.shared.u64 t, %1; cvt.u32.u64 %0, t; }" : "=r"(a) : "l"(p));
    return a;
}
#define CP_ASYNC16(dst, src) \
    asm volatile("cp.async.cg.shared.global [%0], [%1], 16;" :: "r"(dst), "l"(src) : "memory")
#define CP_COMMIT() asm volatile("cp.async.commit_group;" ::: "memory")
#define CP_WAIT(n)  asm volatile("cp.async.wait_group %0;" :: "n"(n) : "memory")

#define LDSM_X4(r0, r1, r2, r3, addr) \
    asm volatile("ldmatrix.sync.aligned.m8n8.x4.shared.b16 {%0,%1,%2,%3}, [%4];" \
                 : "=r"(r0), "=r"(r1), "=r"(r2), "=r"(r3) : "r"(addr))
#define LDSM_X4T(r0, r1, r2, r3, addr) \
    asm volatile("ldmatrix.sync.aligned.m8n8.x4.trans.shared.b16 {%0,%1,%2,%3}, [%4];" \
                 : "=r"(r0), "=r"(r1), "=r"(r2), "=r"(r3) : "r"(addr))

#define MMA16816(C, A, B0, B1) \
    asm volatile("mma.sync.aligned.m16n8k16.row.col.f32.f16.f16.f32 " \
                 "{%0,%1,%2,%3},{%4,%5,%6,%7},{%8,%9},{%0,%1,%2,%3};" \
                 : "+f"((C)[0]), "+f"((C)[1]), "+f"((C)[2]), "+f"((C)[3]) \
                 : "r"((A)[0]), "r"((A)[1]), "r"((A)[2]), "r"((A)[3]), "r"(B0), "r"(B1))

__device__ __forceinline__ float ftanh(float x) {
    x = fminf(fmaxf(x, -12.f), 12.f);
    float e = __expf(2.f * x);
    return __fdividef(e - 1.f, e + 1.f);
}

// ====== prep 1: fold BN scale into Wc, split fp16; ALSO zero g_attlog =======
__global__ void wc_prep_kernel(const float* __restrict__ Wc, const float* __restrict__ bc,
                               const float* __restrict__ gamma, const float* __restrict__ beta,
                               const float* __restrict__ mean, const float* __restrict__ var) {
    int o = blockIdx.x, tid = threadIdx.x;  // 512 blocks x 256 threads
    int zi = o * 256 + tid;
    if (zi < NCOL) g_attlog[zi] = 0.f;
    float sc = gamma[o] * rsqrtf(var[o] + 1e-5f);
    if (tid == 0) g_bi[o] = (bc[o] - mean[o]) * sc + beta[o];
    float4 v = ((const float4*)(Wc + (size_t)o * CIN))[tid];
    v.x *= sc; v.y *= sc; v.z *= sc; v.w *= sc;
    __half h0 = __float2half_rn(v.x), h1 = __float2half_rn(v.y);
    __half h2 = __float2half_rn(v.z), h3 = __float2half_rn(v.w);
    __half l0 = __float2half_rn(v.x - __half2float(h0));
    __half l1 = __float2half_rn(v.y - __half2float(h1));
    __half l2 = __float2half_rn(v.z - __half2float(h2));
    __half l3 = __float2half_rn(v.w - __half2float(h3));
    uint2 uh, ul;
    uh.x = (uint32_t)__half_as_ushort(h0) | ((uint32_t)__half_as_ushort(h1) << 16);
    uh.y = (uint32_t)__half_as_ushort(h2) | ((uint32_t)__half_as_ushort(h3) << 16);
    ul.x = (uint32_t)__half_as_ushort(l0) | ((uint32_t)__half_as_ushort(l1) << 16);
    ul.y = (uint32_t)__half_as_ushort(l2) | ((uint32_t)__half_as_ushort(l3) << 16);
    ((uint2*)g_Wc_hi)[o * 256 + tid] = uh;
    ((uint2*)g_Wc_lo)[o * 256 + tid] = ul;
}

// ====== prep 2: transpose x to [K][N] fp16, vectorized (float4 -> half4) ====
__global__ void x_prep_kernel(const float* __restrict__ x) {
    int g = blockIdx.x * 256 + threadIdx.x;      // < 512*1024*49
    int row = g / 49;                            // (b,k) row
    int q = g - row * 49;                        // float4 index within row
    int b = row >> 10, k = row & 1023;
    float4 v = ((const float4*)x)[(size_t)row * 49 + q];
    __half2 h01 = __floats2half2_rn(v.x, v.y);
    __half2 h23 = __floats2half2_rn(v.z, v.w);
    uint2 u;
    u.x = *(uint32_t*)&h01;
    u.y = *(uint32_t*)&h23;
    *(uint2*)(g_xh + (size_t)k * NCOL + b * HW2 + q * 4) = u;
}

// ---------------- attr tables: 8 x 512, tiny -------------------------------
__global__ void attr_kernel(const float* __restrict__ emb,
                            const float* __restrict__ Wt1, const float* __restrict__ bt1,
                            const float* __restrict__ Wt2, const float* __restrict__ bt2) {
    int a = blockIdx.x;
    __shared__ float e[512];
    int tid = threadIdx.x;
    e[tid]       = emb[a * 512 + tid];
    e[tid + 256] = emb[a * 512 + tid + 256];
    __syncthreads();
    int warp = tid >> 5, lane = tid & 31;
    for (int o = warp; o < 512; o += 8) {
        float s1 = 0.f, s2 = 0.f;
        for (int k = lane; k < 512; k += 32) {
            float ev = e[k];
            s1 = fmaf(ev, Wt1[o * 512 + k], s1);
            s2 = fmaf(ev, Wt2[o * 512 + k], s2);
        }
        #pragma unroll
        for (int off = 16; off; off >>= 1) {
            s1 += __shfl_down_sync(0xffffffffu, s1, off);
            s2 += __shfl_down_sync(0xffffffffu, s2, off);
        }
        if (lane == 0) {
            g_attr1[a * 512 + o] = tanhf(s1 + bt1[o]);
            g_attr2[a * 512 + o] = fmaxf(s2 + bt2[o], 0.f);
        }
    }
}

// ======================= HMMA fused conv+BN+tanh+attn dot ===================
// GEMM M=512(o) x N=100352 x K=1024, fp16 2-product split on tensor cores.
// Grid (4, 1568): blockIdx.x = 128-row M group (fast dim -> B tile L2-shared),
//                 blockIdx.y = 64-col N tile.
// CTA: 128 threads, 4 warps as 2(m) x 2(n); warp tile 64M x 32N; K chunk 32.
// smem stage: Ah[128x80B] Al[128x80B] B[32x144B] = 25088 B; x2 = 50176.
// 4 CTAs/SM -> 16 warps with 4 independent barrier domains.
#define ST_A   10240
#define ST_B   4608
#define ST_BYTES (2 * ST_A + ST_B)   // 25088
#define CONV_SMEM (2 * ST_BYTES)     // 50176

__global__ void __launch_bounds__(128, 4) conv_att_hmma(const int* __restrict__ cidx) {
    extern __shared__ char smem[];
    uint32_t sb = smem_u32(smem);
    int tid = threadIdx.x, wid = tid >> 5, lane = tid & 31;
    int wm = wid & 1, wn = wid >> 1;
    int m0 = blockIdx.x * 128;
    int n0 = blockIdx.y * 64;

    // ---- cp.async offsets ----
    uint32_t a_soff[4], a_doff[4];
    #pragma unroll
    for (int t = 0; t < 4; t++) {
        int i = t * 128 + tid;          // 0..511
        int row = i >> 2, ch = i & 3;
        a_soff[t] = (uint32_t)((m0 + row) * CIN + ch * 8);
        a_doff[t] = (uint32_t)(row * 80 + ch * 16);
    }
    uint32_t b_soff[2], b_doff[2];
    #pragma unroll
    for (int t = 0; t < 2; t++) {
        int i = t * 128 + tid;          // 0..255
        int krow = i >> 3, bch = i & 7;
        b_soff[t] = (uint32_t)krow * NCOL + (uint32_t)(n0 + bch * 8);
        b_doff[t] = 2 * ST_A + (uint32_t)(krow * 144 + bch * 16);
    }

    float acc[4][4][4];
    #pragma unroll
    for (int mi = 0; mi < 4; mi++)
        #pragma unroll
        for (int nj = 0; nj < 4; nj++)
            #pragma unroll
            for (int r = 0; r < 4; r++) acc[mi][nj][r] = 0.f;

    // ldmatrix bases
    uint32_t a_lds = sb + (uint32_t)(wm * 64 + (lane & 15)) * 80 + ((lane >> 4) & 1) * 16;
    uint32_t b_lds = sb + 2 * ST_A + (uint32_t)(lane & 15) * 144 +
                     (uint32_t)(wn * 32 + ((lane >> 4) & 1) * 8) * 2;

    // ---- prologue: stage 0 ----
    #pragma unroll
    for (int t = 0; t < 4; t++) {
        CP_ASYNC16(sb + a_doff[t], g_Wc_hi + a_soff[t]);
        CP_ASYNC16(sb + ST_A + a_doff[t], g_Wc_lo + a_soff[t]);
    }
    #pragma unroll
    for (int t = 0; t < 2; t++) CP_ASYNC16(sb + b_doff[t], g_xh + b_soff[t]);
    CP_COMMIT();

    for (int s = 0; s < 32; s++) {
        uint32_t nbuf = ((s + 1) & 1) * ST_BYTES;
        if (s < 31) {
            uint32_t ka = (uint32_t)(s + 1) * 32;
            size_t kb = (size_t)(s + 1) * 32 * NCOL;
            #pragma unroll
            for (int t = 0; t < 4; t++) {
                CP_ASYNC16(sb + a_doff[t] + nbuf, g_Wc_hi + a_soff[t] + ka);
                CP_ASYNC16(sb + ST_A + a_doff[t] + nbuf, g_Wc_lo + a_soff[t] + ka);
            }
            #pragma unroll
            for (int t = 0; t < 2; t++) CP_ASYNC16(sb + b_doff[t] + nbuf, g_xh + b_soff[t] + kb);
            CP_COMMIT();
            CP_WAIT(1);
        } else {
            CP_WAIT(0);
        }
        __syncthreads();

        uint32_t cbuf = (s & 1) * ST_BYTES;
        #pragma unroll
        for (int ks = 0; ks < 2; ks++) {
            uint32_t b0[4], b1[4];
            uint32_t baddr = b_lds + cbuf + (uint32_t)(ks * 16) * 144;
            LDSM_X4T(b0[0], b0[1], b0[2], b0[3], baddr);        // cols +0..15
            LDSM_X4T(b1[0], b1[1], b1[2], b1[3], baddr + 32);   // cols +16..31
            #pragma unroll
            for (int mi = 0; mi < 4; mi++) {
                uint32_t ah[4], al[4];
                uint32_t aaddr = a_lds + cbuf + (uint32_t)(mi * 16) * 80 + ks * 32;
                LDSM_X4(ah[0], ah[1], ah[2], ah[3], aaddr);
                LDSM_X4(al[0], al[1], al[2], al[3], aaddr + ST_A);
                MMA16816(acc[mi][0], ah, b0[0], b0[1]);
                MMA16816(acc[mi][1], ah, b0[2], b0[3]);
                MMA16816(acc[mi][2], ah, b1[0], b1[1]);
                MMA16816(acc[mi][3], ah, b1[2], b1[3]);
                MMA16816(acc[mi][0], al, b0[0], b0[1]);
                MMA16816(acc[mi][1], al, b0[2], b0[3]);
                MMA16816(acc[mi][2], al, b1[0], b1[1]);
                MMA16816(acc[mi][3], al, b1[2], b1[3]);
            }
        }
        __syncthreads();
    }

    // ---- epilogue: logits[n] += sum_m attr1[c(n)][m] * tanh(D[m][n]+bi[m]) ----
    int b0i = n0 / HW2;
    int ncut = (b0i + 1) * HW2;
    int b1i = (ncut < n0 + 64) ? b0i + 1 : b0i;
    int c0i = cidx[b0i], c1i = cidx[b1i];
    int r0 = lane >> 2;
    int colE = (lane & 3) * 2;

    float accE[4] = {0.f, 0.f, 0.f, 0.f}, accO[4] = {0.f, 0.f, 0.f, 0.f};
    #pragma unroll
    for (int mi = 0; mi < 4; mi++) {
        int mA = m0 + wm * 64 + mi * 16 + r0;
        int mB = mA + 8;
        float biA = g_bi[mA], biB = g_bi[mB];
        float a0A = g_attr1[c0i * 512 + mA], a1A = g_attr1[c1i * 512 + mA];
        float a0B = g_attr1[c0i * 512 + mB], a1B = g_attr1[c1i * 512 + mB];
        #pragma unroll
        for (int nj = 0; nj < 4; nj++) {
            int colg = n0 + wn * 32 + nj * 8 + colE;
            float awAe = (colg < ncut) ? a0A : a1A;
            float awBe = (colg < ncut) ? a0B : a1B;
            float awAo = (colg + 1 < ncut) ? a0A : a1A;
            float awBo = (colg + 1 < ncut) ? a0B : a1B;
            accE[nj] += awAe * ftanh(acc[mi][nj][0] + biA) + awBe * ftanh(acc[mi][nj][2] + biB);
            accO[nj] += awAo * ftanh(acc[mi][nj][1] + biA) + awBo * ftanh(acc[mi][nj][3] + biB);
        }
    }
    // reduce rows: lanes sharing (lane&3)
    #pragma unroll
    for (int off = 4; off <= 16; off <<= 1) {
        #pragma unroll
        for (int nj = 0; nj < 4; nj++) {
            accE[nj] += __shfl_xor_sync(0xffffffffu, accE[nj], off);
            accO[nj] += __shfl_xor_sync(0xffffffffu, accO[nj], off);
        }
    }
    __syncthreads();
    float* sred = (float*)smem;   // [4 warps][32 cols]
    if (lane < 4) {
        #pragma unroll
        for (int nj = 0; nj < 4; nj++) {
            sred[wid * 32 + nj * 8 + colE]     = accE[nj];
            sred[wid * 32 + nj * 8 + colE + 1] = accO[nj];
        }
    }
    __syncthreads();
    if (tid < 64) {
        int wnf = tid >> 5, cl = tid & 31;
        float t = sred[(wnf * 2) * 32 + cl] + sred[(wnf * 2 + 1) * 32 + cl];
        atomicAdd(&g_attlog[n0 + tid], t);
    }
}

// ---------------- spatial softmax per batch --------------------------------
__global__ void softmax_kernel() {
    int b = blockIdx.x, tid = threadIdx.x;
    __shared__ float sh[256];
    float v = (tid < HW2) ? g_attlog[b * HW2 + tid] * 0.044194173824159216f : -1e30f;
    sh[tid] = v;
    __syncthreads();
    for (int s = 128; s; s >>= 1) {
        if (tid < s) sh[tid] = fmaxf(sh[tid], sh[tid + s]);
        __syncthreads();
    }
    float mx = sh[0];
    __syncthreads();
    float e = (tid < HW2) ? expf(v - mx) : 0.f;
    sh[tid] = e;
    __syncthreads();
    for (int s = 128; s; s >>= 1) {
        if (tid < s) sh[tid] += sh[tid + s];
        __syncthreads();
    }
    float inv = 1.f / sh[0];
    if (tid < HW2) g_attp[b * HW2 + tid] = e * inv;
}

// ------ feat[b,c] = sum_hw x[b,c,hw] * p[b,hw]  (fp16 copy, uint2 loads) ----
__global__ void feat_kernel() {
    int b = blockIdx.x;
    __shared__ float p[HW2];
    int tid = threadIdx.x;
    if (tid < HW2) p[tid] = g_attp[b * HW2 + tid];
    __syncthreads();
    int warp = tid >> 5, lane = tid & 31;
    const __half* xb = g_xh + (size_t)b * HW2;
    for (int k = warp; k < CIN; k += 8) {
        const __half* row = xb + (size_t)k * NCOL;
        float sum = 0.f;
        #pragma unroll
        for (int ch = lane; ch < 49; ch += 32) {     // 49 x (4 halfs)
            uint2 u = *(const uint2*)(row + ch * 4);
            __half2 h01 = *(__half2*)&u.x;
            __half2 h23 = *(__half2*)&u.y;
            float2 f01 = __half22float2(h01);
            float2 f23 = __half22float2(h23);
            int hw = ch * 4;
            sum = fmaf(f01.x, p[hw + 0], sum);
            sum = fmaf(f01.y, p[hw + 1], sum);
            sum = fmaf(f23.x, p[hw + 2], sum);
            sum = fmaf(f23.y, p[hw + 3], sum);
        }
        #pragma unroll
        for (int off = 16; off; off >>= 1)
            sum += __shfl_down_sync(0xffffffffu, sum, off);
        if (lane == 0) g_feat[b * CIN + k] = sum;
    }
}

// ---------------- generic 64x64 GEMM: C = act(A @ W^T + bias) --------------
template <int MODE, int ACT, int DST>
__global__ void __launch_bounds__(256) gemm64_kernel(
    const float* __restrict__ W, const float* __restrict__ bias,
    float* __restrict__ Cout, int N, int K, const int* __restrict__ cidx) {
    __shared__ float As[16][64];
    __shared__ float Ws[16][64];
    int tid = threadIdx.x;
    int n0 = blockIdx.x * 64, m0 = blockIdx.y * 64;
    int lr = tid >> 2;
    int lk = (tid & 3) << 2;
    int tm = tid >> 4, tn = tid & 15;

    float acc[4][4];
    #pragma unroll
    for (int i = 0; i < 4; i++)
        #pragma unroll
        for (int j = 0; j < 4; j++) acc[i][j] = 0.f;

    for (int k0 = 0; k0 < K; k0 += 16) {
        int m = m0 + lr, k = k0 + lk;
        float4 av;
        if (MODE == 0) {
            av = *(const float4*)(g_h1 + (size_t)m * 512 + k);
        } else if (MODE == 1) {
            if (k < 1024) av = *(const float4*)(g_feat + (size_t)m * 1024 + k);
            else          av = *(const float4*)(g_attr2 + cidx[m] * 512 + (k - 1024));
        } else {
            float4 f = *(const float4*)(g_feat + (size_t)m * 1024 + k);
            float4 g = *(const float4*)(g_mask + (size_t)m * 1024 + k);
            av = make_float4(f.x * g.x, f.y * g.y, f.z * g.z, f.w * g.w);
        }
        As[lk + 0][lr] = av.x; As[lk + 1][lr] = av.y;
        As[lk + 2][lr] = av.z; As[lk + 3][lr] = av.w;

        float4 wv = *(const float4*)(W + (size_t)(n0 + lr) * K + k);
        Ws[lk + 0][lr] = wv.x; Ws[lk + 1][lr] = wv.y;
        Ws[lk + 2][lr] = wv.z; Ws[lk + 3][lr] = wv.w;
        __syncthreads();
        #pragma unroll
        for (int kk = 0; kk < 16; kk++) {
            float a[4], b[4];
            *(float4*)a = *(const float4*)&As[kk][tm * 4];
            *(float4*)b = *(const float4*)&Ws[kk][tn * 4];
            #pragma unroll
            for (int i = 0; i < 4; i++)
                #pragma unroll
                for (int j = 0; j < 4; j++)
                    acc[i][j] = fmaf(a[i], b[j], acc[i][j]);
        }
        __syncthreads();
    }

    float* Cp = (DST == 0) ? g_h1 : (DST == 1) ? g_mask : Cout;
    #pragma unroll
    for (int j = 0; j < 4; j++) {
        int n = n0 + tn * 4 + j;
        float bv = bias[n];
        #pragma unroll
        for (int i = 0; i < 4; i++) {
            int m = m0 + tm * 4 + i;
            float v = acc[i][j] + bv;
            if (ACT == 1) v = fmaxf(v, 0.f);
            else if (ACT == 2) v = 1.f / (1.f + expf(-v));
            Cp[(size_t)m * N + n] = v;
        }
    }
}

// ---------------- row-wise L2 normalize in place ----------------------------
__global__ void l2norm_kernel(float* __restrict__ out) {
    int b = blockIdx.x, tid = threadIdx.x;
    __shared__ float sh[256];
    float s = 0.f;
    for (int i = tid; i < EMBD; i += 256) {
        float v = out[(size_t)b * EMBD + i];
        s = fmaf(v, v, s);
    }
    sh[tid] = s;
    __syncthreads();
    for (int st = 128; st; st >>= 1) {
        if (tid < st) sh[tid] += sh[tid + st];
        __syncthreads();
    }
    float inv = 1.f / sqrtf(sh[0]);
    for (int i = tid; i < EMBD; i += 256) out[(size_t)b * EMBD + i] *= inv;
}

// ---------------- launch ----------------------------------------------------
extern "C" void kernel_launch(void* const* d_in, const int* in_sizes, int n_in,
                              void* d_out, int out_size) {
    const float* x        = (const float*)d_in[0];
    const int*   c        = (const int*)  d_in[1];
    const float* attr_emb = (const float*)d_in[2];
    const float* Wt1      = (const float*)d_in[3];
    const float* bt1      = (const float*)d_in[4];
    const float* Wc       = (const float*)d_in[5];
    const float* bc       = (const float*)d_in[6];
    const float* bn_gamma = (const float*)d_in[7];
    const float* bn_beta  = (const float*)d_in[8];
    const float* bn_mean  = (const float*)d_in[9];
    const float* bn_var   = (const float*)d_in[10];
    const float* Wt2      = (const float*)d_in[11];
    const float* bt2      = (const float*)d_in[12];
    const float* W1       = (const float*)d_in[13];
    const float* b1       = (const float*)d_in[14];
    const float* W2       = (const float*)d_in[15];
    const float* b2       = (const float*)d_in[16];
    const float* Wf       = (const float*)d_in[17];
    const float* bf       = (const float*)d_in[18];
    float* out = (float*)d_out;

    static bool attr_set = false;
    if (!attr_set) {
        cudaFuncSetAttribute(conv_att_hmma, cudaFuncAttributeMaxDynamicSharedMemorySize, CONV_SMEM);
        attr_set = true;
    }

    wc_prep_kernel<<<CMID, 256>>>(Wc, bc, bn_gamma, bn_beta, bn_mean, bn_var);  // also zeroes attlog
    x_prep_kernel<<<BATCH * CIN * 49 / 256, 256>>>(x);
    attr_kernel<<<8, 256>>>(attr_emb, Wt1, bt1, Wt2, bt2);
    conv_att_hmma<<<dim3(4, NCOL / 64), 128, CONV_SMEM>>>(c);   // 4th launch -> ncu target
    softmax_kernel<<<BATCH, 256>>>();
    feat_kernel<<<BATCH, 256>>>();
    gemm64_kernel<1, 1, 0><<<dim3(512 / 64, BATCH / 64), 256>>>(W1, b1, nullptr, 512, 1536, c);
    gemm64_kernel<0, 2, 1><<<dim3(1024 / 64, BATCH / 64), 256>>>(W2, b2, nullptr, 1024, 512, c);
    gemm64_kernel<2, 0, 2><<<dim3(1024 / 64, BATCH / 64), 256>>>(Wf, bf, out, 1024, 1024, c);
    l2norm_kernel<<<BATCH, 256>>>(out);
}

// round 7
// speedup vs baseline: 3.4250x; 1.3658x over previous
#include <cuda_runtime.h>
#include <cuda_fp16.h>
#include <math.h>
#include <stdint.h>

#define BATCH 512
#define CIN   1024
#define CMID  512
#define HW2   196
#define EMBD  1024
#define NCOL  (BATCH * HW2)   // 100352 = 1568 * 64

// ---------------- scratch (device globals; no allocations allowed) ----------
__device__ float g_attr1[8 * 512];
__device__ float g_attr2[8 * 512];
__device__ float g_attlog[NCOL];
__device__ float g_attp[NCOL];
__device__ float g_feat[BATCH * 1024];
__device__ float g_h1[BATCH * 512];
__device__ float g_mask[BATCH * 1024];
__device__ float g_bi[CMID];
__device__ __align__(16) __half g_Wc_h[CMID * CIN];
// x transposed to [K][N] fp16 (205 MB)
__device__ __align__(16) __half g_xh[(size_t)CIN * NCOL];

// ======================= PTX helpers (non-'a' features only) ================
__device__ __forceinline__ uint32_t smem_u32(const void* p) {
    uint32_t a;
    asm("{ .reg .u64 t; cvta.to.shared.u64 t, %1; cvt.u32.u64 %0, t; }" : "=r"(a) : "l"(p));
    return a;
}
#define CP_ASYNC16(dst, src) \
    asm volatile("cp.async.cg.shared.global [%0], [%1], 16;" :: "r"(dst), "l"(src) : "memory")
#define CP_COMMIT() asm volatile("cp.async.commit_group;" ::: "memory")
#define CP_WAIT(n)  asm volatile("cp.async.wait_group %0;" :: "n"(n) : "memory")

#define LDSM_X4(r0, r1, r2, r3, addr) \
    asm volatile("ldmatrix.sync.aligned.m8n8.x4.shared.b16 {%0,%1,%2,%3}, [%4];" \
                 : "=r"(r0), "=r"(r1), "=r"(r2), "=r"(r3) : "r"(addr))
#define LDSM_X4T(r0, r1, r2, r3, addr) \
    asm volatile("ldmatrix.sync.aligned.m8n8.x4.trans.shared.b16 {%0,%1,%2,%3}, [%4];" \
                 : "=r"(r0), "=r"(r1), "=r"(r2), "=r"(r3) : "r"(addr))

#define MMA16816(C, A, B0, B1) \
    asm volatile("mma.sync.aligned.m16n8k16.row.col.f32.f16.f16.f32 " \
                 "{%0,%1,%2,%3},{%4,%5,%6,%7},{%8,%9},{%0,%1,%2,%3};" \
                 : "+f"((C)[0]), "+f"((C)[1]), "+f"((C)[2]), "+f"((C)[3]) \
                 : "r"((A)[0]), "r"((A)[1]), "r"((A)[2]), "r"((A)[3]), "r"(B0), "r"(B1))

__device__ __forceinline__ float ftanh(float x) {
    x = fminf(fmaxf(x, -12.f), 12.f);
    float e = __expf(2.f * x);
    return __fdividef(e - 1.f, e + 1.f);
}

// ====== prep 1: fold BN scale into Wc -> fp16; ALSO zero g_attlog ===========
__global__ void wc_prep_kernel(const float* __restrict__ Wc, const float* __restrict__ bc,
                               const float* __restrict__ gamma, const float* __restrict__ beta,
                               const float* __restrict__ mean, const float* __restrict__ var) {
    int o = blockIdx.x, tid = threadIdx.x;  // 512 blocks x 256 threads
    int zi = o * 256 + tid;
    if (zi < NCOL) g_attlog[zi] = 0.f;
    float sc = gamma[o] * rsqrtf(var[o] + 1e-5f);
    if (tid == 0) g_bi[o] = (bc[o] - mean[o]) * sc + beta[o];
    float4 v = ((const float4*)(Wc + (size_t)o * CIN))[tid];
    __half2 h01 = __floats2half2_rn(v.x * sc, v.y * sc);
    __half2 h23 = __floats2half2_rn(v.z * sc, v.w * sc);
    uint2 u;
    u.x = *(uint32_t*)&h01;
    u.y = *(uint32_t*)&h23;
    ((uint2*)g_Wc_h)[o * 256 + tid] = u;
}

// ====== prep 2: transpose x to [K][N] fp16, vectorized (float4 -> half4) ====
__global__ void x_prep_kernel(const float* __restrict__ x) {
    int g = blockIdx.x * 256 + threadIdx.x;      // < 512*1024*49
    int row = g / 49;                            // (b,k) row
    int q = g - row * 49;                        // float4 index within row
    int b = row >> 10, k = row & 1023;
    float4 v = ((const float4*)x)[(size_t)row * 49 + q];
    __half2 h01 = __floats2half2_rn(v.x, v.y);
    __half2 h23 = __floats2half2_rn(v.z, v.w);
    uint2 u;
    u.x = *(uint32_t*)&h01;
    u.y = *(uint32_t*)&h23;
    *(uint2*)(g_xh + (size_t)k * NCOL + b * HW2 + q * 4) = u;
}

// ---------------- attr tables: 8 x 512, tiny -------------------------------
__global__ void attr_kernel(const float* __restrict__ emb,
                            const float* __restrict__ Wt1, const float* __restrict__ bt1,
                            const float* __restrict__ Wt2, const float* __restrict__ bt2) {
    int a = blockIdx.x;
    __shared__ float e[512];
    int tid = threadIdx.x;
    e[tid]       = emb[a * 512 + tid];
    e[tid + 256] = emb[a * 512 + tid + 256];
    __syncthreads();
    int warp = tid >> 5, lane = tid & 31;
    for (int o = warp; o < 512; o += 8) {
        float s1 = 0.f, s2 = 0.f;
        for (int k = lane; k < 512; k += 32) {
            float ev = e[k];
            s1 = fmaf(ev, Wt1[o * 512 + k], s1);
            s2 = fmaf(ev, Wt2[o * 512 + k], s2);
        }
        #pragma unroll
        for (int off = 16; off; off >>= 1) {
            s1 += __shfl_down_sync(0xffffffffu, s1, off);
            s2 += __shfl_down_sync(0xffffffffu, s2, off);
        }
        if (lane == 0) {
            g_attr1[a * 512 + o] = tanhf(s1 + bt1[o]);
            g_attr2[a * 512 + o] = fmaxf(s2 + bt2[o], 0.f);
        }
    }
}

// ======================= HMMA fused conv+BN+tanh+attn dot ===================
// GEMM M=512(o) x N=100352 x K=1024, single fp16 product on tensor cores.
// Grid (4, 1568): blockIdx.x = 128-row M group (fast -> B tile shared in L2),
//                 blockIdx.y = 64-col N tile.
// CTA: 128 threads, 4 warps 2(m) x 2(n); warp tile 64M x 32N; K chunk 32.
// 3-stage cp.async pipeline, ONE __syncthreads per chunk:
//   wait(1) -> sync -> prefetch chunk s+2 -> compute chunk s.
// smem stage: A[128x80B]=10240 + B[32x144B]=4608 = 14848; x3 = 44544 -> 4 CTA/SM.
#define ST_A   10240
#define ST_B   4608
#define ST_BYTES (ST_A + ST_B)        // 14848
#define CONV_SMEM (3 * ST_BYTES)      // 44544

__global__ void __launch_bounds__(128, 4) conv_att_hmma(const int* __restrict__ cidx) {
    extern __shared__ char smem[];
    uint32_t sb = smem_u32(smem);
    int tid = threadIdx.x, wid = tid >> 5, lane = tid & 31;
    int wm = wid & 1, wn = wid >> 1;
    int m0 = blockIdx.x * 128;
    int n0 = blockIdx.y * 64;

    // ---- cp.async offsets ----
    uint32_t a_soff[4], a_doff[4];
    #pragma unroll
    for (int t = 0; t < 4; t++) {
        int i = t * 128 + tid;          // 0..511
        int row = i >> 2, ch = i & 3;
        a_soff[t] = (uint32_t)((m0 + row) * CIN + ch * 8);
        a_doff[t] = (uint32_t)(row * 80 + ch * 16);
    }
    uint32_t b_soff[2], b_doff[2];
    #pragma unroll
    for (int t = 0; t < 2; t++) {
        int i = t * 128 + tid;          // 0..255
        int krow = i >> 3, bch = i & 7;
        b_soff[t] = (uint32_t)krow * NCOL + (uint32_t)(n0 + bch * 8);
        b_doff[t] = ST_A + (uint32_t)(krow * 144 + bch * 16);
    }

    float acc[4][4][4];
    #pragma unroll
    for (int mi = 0; mi < 4; mi++)
        #pragma unroll
        for (int nj = 0; nj < 4; nj++)
            #pragma unroll
            for (int r = 0; r < 4; r++) acc[mi][nj][r] = 0.f;

    // ldmatrix bases
    uint32_t a_lds = sb + (uint32_t)(wm * 64 + (lane & 15)) * 80 + ((lane >> 4) & 1) * 16;
    uint32_t b_lds = sb + ST_A + (uint32_t)(lane & 15) * 144 +
                     (uint32_t)(wn * 32 + ((lane >> 4) & 1) * 8) * 2;

    // ---- prologue: stages 0 and 1 ----
    #pragma unroll
    for (int st = 0; st < 2; st++) {
        uint32_t buf = (uint32_t)st * ST_BYTES;
        uint32_t ka = (uint32_t)st * 32;
        size_t kb = (size_t)st * 32 * NCOL;
        #pragma unroll
        for (int t = 0; t < 4; t++) CP_ASYNC16(sb + a_doff[t] + buf, g_Wc_h + a_soff[t] + ka);
        #pragma unroll
        for (int t = 0; t < 2; t++) CP_ASYNC16(sb + b_doff[t] + buf, g_xh + b_soff[t] + kb);
        CP_COMMIT();
    }

    int cstage = 0;   // s % 3
    for (int s = 0; s < 32; s++) {
        if (s < 31) { CP_WAIT(1); } else { CP_WAIT(0); }
        __syncthreads();

        if (s < 30) {
            int pst = cstage + 2; if (pst >= 3) pst -= 3;
            uint32_t buf = (uint32_t)pst * ST_BYTES;
            uint32_t ka = (uint32_t)(s + 2) * 32;
            size_t kb = (size_t)(s + 2) * 32 * NCOL;
            #pragma unroll
            for (int t = 0; t < 4; t++) CP_ASYNC16(sb + a_doff[t] + buf, g_Wc_h + a_soff[t] + ka);
            #pragma unroll
            for (int t = 0; t < 2; t++) CP_ASYNC16(sb + b_doff[t] + buf, g_xh + b_soff[t] + kb);
            CP_COMMIT();
        }

        uint32_t cbuf = (uint32_t)cstage * ST_BYTES;
        #pragma unroll
        for (int ks = 0; ks < 2; ks++) {
            uint32_t b0[4], b1[4];
            uint32_t baddr = b_lds + cbuf + (uint32_t)(ks * 16) * 144;
            LDSM_X4T(b0[0], b0[1], b0[2], b0[3], baddr);        // cols +0..15
            LDSM_X4T(b1[0], b1[1], b1[2], b1[3], baddr + 32);   // cols +16..31
            #pragma unroll
            for (int mi = 0; mi < 4; mi++) {
                uint32_t ah[4];
                uint32_t aaddr = a_lds + cbuf + (uint32_t)(mi * 16) * 80 + ks * 32;
                LDSM_X4(ah[0], ah[1], ah[2], ah[3], aaddr);
                MMA16816(acc[mi][0], ah, b0[0], b0[1]);
                MMA16816(acc[mi][1], ah, b0[2], b0[3]);
                MMA16816(acc[mi][2], ah, b1[0], b1[1]);
                MMA16816(acc[mi][3], ah, b1[2], b1[3]);
            }
        }
        if (++cstage == 3) cstage = 0;
    }
    __syncthreads();

    // ---- epilogue: logits[n] += sum_m attr1[c(n)][m] * tanh(D[m][n]+bi[m]) ----
    int b0i = n0 / HW2;
    int ncut = (b0i + 1) * HW2;
    int b1i = (ncut < n0 + 64) ? b0i + 1 : b0i;
    int c0i = cidx[b0i], c1i = cidx[b1i];
    int r0 = lane >> 2;
    int colE = (lane & 3) * 2;

    float accE[4] = {0.f, 0.f, 0.f, 0.f}, accO[4] = {0.f, 0.f, 0.f, 0.f};
    #pragma unroll
    for (int mi = 0; mi < 4; mi++) {
        int mA = m0 + wm * 64 + mi * 16 + r0;
        int mB = mA + 8;
        float biA = g_bi[mA], biB = g_bi[mB];
        float a0A = g_attr1[c0i * 512 + mA], a1A = g_attr1[c1i * 512 + mA];
        float a0B = g_attr1[c0i * 512 + mB], a1B = g_attr1[c1i * 512 + mB];
        #pragma unroll
        for (int nj = 0; nj < 4; nj++) {
            int colg = n0 + wn * 32 + nj * 8 + colE;
            float awAe = (colg < ncut) ? a0A : a1A;
            float awBe = (colg < ncut) ? a0B : a1B;
            float awAo = (colg + 1 < ncut) ? a0A : a1A;
            float awBo = (colg + 1 < ncut) ? a0B : a1B;
            accE[nj] += awAe * ftanh(acc[mi][nj][0] + biA) + awBe * ftanh(acc[mi][nj][2] + biB);
            accO[nj] += awAo * ftanh(acc[mi][nj][1] + biA) + awBo * ftanh(acc[mi][nj][3] + biB);
        }
    }
    // reduce rows: lanes sharing (lane&3)
    #pragma unroll
    for (int off = 4; off <= 16; off <<= 1) {
        #pragma unroll
        for (int nj = 0; nj < 4; nj++) {
            accE[nj] += __shfl_xor_sync(0xffffffffu, accE[nj], off);
            accO[nj] += __shfl_xor_sync(0xffffffffu, accO[nj], off);
        }
    }
    float* sred = (float*)smem;   // [4 warps][32 cols]
    if (lane < 4) {
        #pragma unroll
        for (int nj = 0; nj < 4; nj++) {
            sred[wid * 32 + nj * 8 + colE]     = accE[nj];
            sred[wid * 32 + nj * 8 + colE + 1] = accO[nj];
        }
    }
    __syncthreads();
    if (tid < 64) {
        int wnf = tid >> 5, cl = tid & 31;
        float t = sred[(wnf * 2) * 32 + cl] + sred[(wnf * 2 + 1) * 32 + cl];
        atomicAdd(&g_attlog[n0 + tid], t);
    }
}

// ---------------- spatial softmax per batch --------------------------------
__global__ void softmax_kernel() {
    int b = blockIdx.x, tid = threadIdx.x;
    __shared__ float sh[256];
    float v = (tid < HW2) ? g_attlog[b * HW2 + tid] * 0.044194173824159216f : -1e30f;
    sh[tid] = v;
    __syncthreads();
    for (int s = 128; s; s >>= 1) {
        if (tid < s) sh[tid] = fmaxf(sh[tid], sh[tid + s]);
        __syncthreads();
    }
    float mx = sh[0];
    __syncthreads();
    float e = (tid < HW2) ? expf(v - mx) : 0.f;
    sh[tid] = e;
    __syncthreads();
    for (int s = 128; s; s >>= 1) {
        if (tid < s) sh[tid] += sh[tid + s];
        __syncthreads();
    }
    float inv = 1.f / sh[0];
    if (tid < HW2) g_attp[b * HW2 + tid] = e * inv;
}

// ------ feat[b,c] = sum_hw x[b,c,hw] * p[b,hw]  (fp16 copy, uint2 loads) ----
__global__ void feat_kernel() {
    int b = blockIdx.x;
    __shared__ float p[HW2];
    int tid = threadIdx.x;
    if (tid < HW2) p[tid] = g_attp[b * HW2 + tid];
    __syncthreads();
    int warp = tid >> 5, lane = tid & 31;
    const __half* xb = g_xh + (size_t)b * HW2;
    for (int k = warp; k < CIN; k += 8) {
        const __half* row = xb + (size_t)k * NCOL;
        float sum = 0.f;
        #pragma unroll
        for (int ch = lane; ch < 49; ch += 32) {     // 49 x (4 halfs)
            uint2 u = *(const uint2*)(row + ch * 4);
            __half2 h01 = *(__half2*)&u.x;
            __half2 h23 = *(__half2*)&u.y;
            float2 f01 = __half22float2(h01);
            float2 f23 = __half22float2(h23);
            int hw = ch * 4;
            sum = fmaf(f01.x, p[hw + 0], sum);
            sum = fmaf(f01.y, p[hw + 1], sum);
            sum = fmaf(f23.x, p[hw + 2], sum);
            sum = fmaf(f23.y, p[hw + 3], sum);
        }
        #pragma unroll
        for (int off = 16; off; off >>= 1)
            sum += __shfl_down_sync(0xffffffffu, sum, off);
        if (lane == 0) g_feat[b * CIN + k] = sum;
    }
}

// ---------------- generic 64x64 GEMM: C = act(A @ W^T + bias) --------------
template <int MODE, int ACT, int DST>
__global__ void __launch_bounds__(256) gemm64_kernel(
    const float* __restrict__ W, const float* __restrict__ bias,
    float* __restrict__ Cout, int N, int K, const int* __restrict__ cidx) {
    __shared__ float As[16][64];
    __shared__ float Ws[16][64];
    int tid = threadIdx.x;
    int n0 = blockIdx.x * 64, m0 = blockIdx.y * 64;
    int lr = tid >> 2;
    int lk = (tid & 3) << 2;
    int tm = tid >> 4, tn = tid & 15;

    float acc[4][4];
    #pragma unroll
    for (int i = 0; i < 4; i++)
        #pragma unroll
        for (int j = 0; j < 4; j++) acc[i][j] = 0.f;

    for (int k0 = 0; k0 < K; k0 += 16) {
        int m = m0 + lr, k = k0 + lk;
        float4 av;
        if (MODE == 0) {
            av = *(const float4*)(g_h1 + (size_t)m * 512 + k);
        } else if (MODE == 1) {
            if (k < 1024) av = *(const float4*)(g_feat + (size_t)m * 1024 + k);
            else          av = *(const float4*)(g_attr2 + cidx[m] * 512 + (k - 1024));
        } else {
            float4 f = *(const float4*)(g_feat + (size_t)m * 1024 + k);
            float4 g = *(const float4*)(g_mask + (size_t)m * 1024 + k);
            av = make_float4(f.x * g.x, f.y * g.y, f.z * g.z, f.w * g.w);
        }
        As[lk + 0][lr] = av.x; As[lk + 1][lr] = av.y;
        As[lk + 2][lr] = av.z; As[lk + 3][lr] = av.w;

        float4 wv = *(const float4*)(W + (size_t)(n0 + lr) * K + k);
        Ws[lk + 0][lr] = wv.x; Ws[lk + 1][lr] = wv.y;
        Ws[lk + 2][lr] = wv.z; Ws[lk + 3][lr] = wv.w;
        __syncthreads();
        #pragma unroll
        for (int kk = 0; kk < 16; kk++) {
            float a[4], b[4];
            *(float4*)a = *(const float4*)&As[kk][tm * 4];
            *(float4*)b = *(const float4*)&Ws[kk][tn * 4];
            #pragma unroll
            for (int i = 0; i < 4; i++)
                #pragma unroll
                for (int j = 0; j < 4; j++)
                    acc[i][j] = fmaf(a[i], b[j], acc[i][j]);
        }
        __syncthreads();
    }

    float* Cp = (DST == 0) ? g_h1 : (DST == 1) ? g_mask : Cout;
    #pragma unroll
    for (int j = 0; j < 4; j++) {
        int n = n0 + tn * 4 + j;
        float bv = bias[n];
        #pragma unroll
        for (int i = 0; i < 4; i++) {
            int m = m0 + tm * 4 + i;
            float v = acc[i][j] + bv;
            if (ACT == 1) v = fmaxf(v, 0.f);
            else if (ACT == 2) v = 1.f / (1.f + expf(-v));
            Cp[(size_t)m * N + n] = v;
        }
    }
}

// ---------------- row-wise L2 normalize in place ----------------------------
__global__ void l2norm_kernel(float* __restrict__ out) {
    int b = blockIdx.x, tid = threadIdx.x;
    __shared__ float sh[256];
    float s = 0.f;
    for (int i = tid; i < EMBD; i += 256) {
        float v = out[(size_t)b * EMBD + i];
        s = fmaf(v, v, s);
    }
    sh[tid] = s;
    __syncthreads();
    for (int st = 128; st; st >>= 1) {
        if (tid < st) sh[tid] += sh[tid + st];
        __syncthreads();
    }
    float inv = 1.f / sqrtf(sh[0]);
    for (int i = tid; i < EMBD; i += 256) out[(size_t)b * EMBD + i] *= inv;
}

// ---------------- launch ----------------------------------------------------
extern "C" void kernel_launch(void* const* d_in, const int* in_sizes, int n_in,
                              void* d_out, int out_size) {
    const float* x        = (const float*)d_in[0];
    const int*   c        = (const int*)  d_in[1];
    const float* attr_emb = (const float*)d_in[2];
    const float* Wt1      = (const float*)d_in[3];
    const float* bt1      = (const float*)d_in[4];
    const float* Wc       = (const float*)d_in[5];
    const float* bc       = (const float*)d_in[6];
    const float* bn_gamma = (const float*)d_in[7];
    const float* bn_beta  = (const float*)d_in[8];
    const float* bn_mean  = (const float*)d_in[9];
    const float* bn_var   = (const float*)d_in[10];
    const float* Wt2      = (const float*)d_in[11];
    const float* bt2      = (const float*)d_in[12];
    const float* W1       = (const float*)d_in[13];
    const float* b1       = (const float*)d_in[14];
    const float* W2       = (const float*)d_in[15];
    const float* b2       = (const float*)d_in[16];
    const float* Wf       = (const float*)d_in[17];
    const float* bf       = (const float*)d_in[18];
    float* out = (float*)d_out;

    static bool attr_set = false;
    if (!attr_set) {
        cudaFuncSetAttribute(conv_att_hmma, cudaFuncAttributeMaxDynamicSharedMemorySize, CONV_SMEM);
        attr_set = true;
    }

    wc_prep_kernel<<<CMID, 256>>>(Wc, bc, bn_gamma, bn_beta, bn_mean, bn_var);  // also zeroes attlog
    x_prep_kernel<<<BATCH * CIN * 49 / 256, 256>>>(x);
    attr_kernel<<<8, 256>>>(attr_emb, Wt1, bt1, Wt2, bt2);
    conv_att_hmma<<<dim3(4, NCOL / 64), 128, CONV_SMEM>>>(c);   // 4th launch -> ncu target
    softmax_kernel<<<BATCH, 256>>>();
    feat_kernel<<<BATCH, 256>>>();
    gemm64_kernel<1, 1, 0><<<dim3(512 / 64, BATCH / 64), 256>>>(W1, b1, nullptr, 512, 1536, c);
    gemm64_kernel<0, 2, 1><<<dim3(1024 / 64, BATCH / 64), 256>>>(W2, b2, nullptr, 1024, 512, c);
    gemm64_kernel<2, 0, 2><<<dim3(1024 / 64, BATCH / 64), 256>>>(Wf, bf, out, 1024, 1024, c);
    l2norm_kernel<<<BATCH, 256>>>(out);
}

// round 8
// speedup vs baseline: 3.8493x; 1.1239x over previous
#include <cuda_runtime.h>
#include <cuda_fp16.h>
#include <math.h>
#include <stdint.h>

#define BATCH 512
#define CIN   1024
#define CMID  512
#define HW2   196
#define EMBD  1024
#define NCOL  (BATCH * HW2)   // 100352 = 1568 * 64

// ---------------- scratch (device globals; no allocations allowed) ----------
__device__ float g_attr1[8 * 512];
__device__ float g_attr2[8 * 512];
__device__ float g_attlog[NCOL];
__device__ float g_feat[BATCH * 1024];
__device__ float g_bi[CMID];
__device__ __align__(16) __half g_Wc_h[CMID * CIN];
__device__ __align__(16) __half g_xh[(size_t)CIN * NCOL];   // x^T [K][N] fp16
// tail-GEMM weights, fp16 hi/lo
__device__ __align__(16) __half g_w1h[512 * 1536], g_w1l[512 * 1536];
__device__ __align__(16) __half g_w2h[1024 * 512], g_w2l[1024 * 512];
__device__ __align__(16) __half g_w3h[1024 * 1024], g_w3l[1024 * 1024];
// tail-GEMM activations, fp16 hi/lo
__device__ __align__(16) __half g_in1h[512 * 1536], g_in1l[512 * 1536];
__device__ __align__(16) __half g_h1h[512 * 512],  g_h1l[512 * 512];
__device__ __align__(16) __half g_fmh[512 * 1024], g_fml[512 * 1024];

// ======================= PTX helpers (non-'a' features only) ================
__device__ __forceinline__ uint32_t smem_u32(const void* p) {
    uint32_t a;
    asm("{ .reg .u64 t; cvta.to.shared.u64 t, %1; cvt.u32.u64 %0, t; }" : "=r"(a) : "l"(p));
    return a;
}
#define CP_ASYNC16(dst, src) \
    asm volatile("cp.async.cg.shared.global [%0], [%1], 16;" :: "r"(dst), "l"(src) : "memory")
#define CP_COMMIT() asm volatile("cp.async.commit_group;" ::: "memory")
#define CP_WAIT(n)  asm volatile("cp.async.wait_group %0;" :: "n"(n) : "memory")

#define LDSM_X4(r0, r1, r2, r3, addr) \
    asm volatile("ldmatrix.sync.aligned.m8n8.x4.shared.b16 {%0,%1,%2,%3}, [%4];" \
                 : "=r"(r0), "=r"(r1), "=r"(r2), "=r"(r3) : "r"(addr))
#define LDSM_X4T(r0, r1, r2, r3, addr) \
    asm volatile("ldmatrix.sync.aligned.m8n8.x4.trans.shared.b16 {%0,%1,%2,%3}, [%4];" \
                 : "=r"(r0), "=r"(r1), "=r"(r2), "=r"(r3) : "r"(addr))

#define MMA16816(C, A, B0, B1) \
    asm volatile("mma.sync.aligned.m16n8k16.row.col.f32.f16.f16.f32 " \
                 "{%0,%1,%2,%3},{%4,%5,%6,%7},{%8,%9},{%0,%1,%2,%3};" \
                 : "+f"((C)[0]), "+f"((C)[1]), "+f"((C)[2]), "+f"((C)[3]) \
                 : "r"((A)[0]), "r"((A)[1]), "r"((A)[2]), "r"((A)[3]), "r"(B0), "r"(B1))

__device__ __forceinline__ float ftanh(float x) {
    x = fminf(fmaxf(x, -12.f), 12.f);
    float e = __expf(2.f * x);
    return __fdividef(e - 1.f, e + 1.f);
}
__device__ __forceinline__ void split16(float v, __half& h, __half& l) {
    h = __float2half_rn(v);
    l = __float2half_rn(v - __half2float(h));
}

// ====== prep 1: fold BN scale into Wc -> fp16; ALSO zero g_attlog ===========
__global__ void wc_prep_kernel(const float* __restrict__ Wc, const float* __restrict__ bc,
                               const float* __restrict__ gamma, const float* __restrict__ beta,
                               const float* __restrict__ mean, const float* __restrict__ var) {
    int o = blockIdx.x, tid = threadIdx.x;
    int zi = o * 256 + tid;
    if (zi < NCOL) g_attlog[zi] = 0.f;
    float sc = gamma[o] * rsqrtf(var[o] + 1e-5f);
    if (tid == 0) g_bi[o] = (bc[o] - mean[o]) * sc + beta[o];
    float4 v = ((const float4*)(Wc + (size_t)o * CIN))[tid];
    __half2 h01 = __floats2half2_rn(v.x * sc, v.y * sc);
    __half2 h23 = __floats2half2_rn(v.z * sc, v.w * sc);
    uint2 u;
    u.x = *(uint32_t*)&h01;
    u.y = *(uint32_t*)&h23;
    ((uint2*)g_Wc_h)[o * 256 + tid] = u;
}

// ====== prep 2: transpose x to [K][N] fp16 ==================================
__global__ void x_prep_kernel(const float* __restrict__ x) {
    int g = blockIdx.x * 256 + threadIdx.x;
    int row = g / 49;
    int q = g - row * 49;
    int b = row >> 10, k = row & 1023;
    float4 v = ((const float4*)x)[(size_t)row * 49 + q];
    __half2 h01 = __floats2half2_rn(v.x, v.y);
    __half2 h23 = __floats2half2_rn(v.z, v.w);
    uint2 u;
    u.x = *(uint32_t*)&h01;
    u.y = *(uint32_t*)&h23;
    *(uint2*)(g_xh + (size_t)k * NCOL + b * HW2 + q * 4) = u;
}

// ====== prep 3: split a weight matrix into fp16 hi/lo =======================
template <int W>
__global__ void wsplit_kernel(const float* __restrict__ src) {
    __half* dh = (W == 0) ? g_w1h : (W == 1) ? g_w2h : g_w3h;
    __half* dl = (W == 0) ? g_w1l : (W == 1) ? g_w2l : g_w3l;
    int i = blockIdx.x * 256 + threadIdx.x;   // float4 index
    float4 v = ((const float4*)src)[i];
    __half h0, h1, h2, h3, l0, l1, l2, l3;
    split16(v.x, h0, l0); split16(v.y, h1, l1);
    split16(v.z, h2, l2); split16(v.w, h3, l3);
    __half2 hh01 = __halves2half2(h0, h1), hh23 = __halves2half2(h2, h3);
    __half2 ll01 = __halves2half2(l0, l1), ll23 = __halves2half2(l2, l3);
    uint2 uh, ul;
    uh.x = *(uint32_t*)&hh01; uh.y = *(uint32_t*)&hh23;
    ul.x = *(uint32_t*)&ll01; ul.y = *(uint32_t*)&ll23;
    ((uint2*)dh)[i] = uh;
    ((uint2*)dl)[i] = ul;
}

// ---------------- attr tables: 8 x 512, tiny -------------------------------
__global__ void attr_kernel(const float* __restrict__ emb,
                            const float* __restrict__ Wt1, const float* __restrict__ bt1,
                            const float* __restrict__ Wt2, const float* __restrict__ bt2) {
    int a = blockIdx.x;
    __shared__ float e[512];
    int tid = threadIdx.x;
    e[tid]       = emb[a * 512 + tid];
    e[tid + 256] = emb[a * 512 + tid + 256];
    __syncthreads();
    int warp = tid >> 5, lane = tid & 31;
    for (int o = warp; o < 512; o += 8) {
        float s1 = 0.f, s2 = 0.f;
        for (int k = lane; k < 512; k += 32) {
            float ev = e[k];
            s1 = fmaf(ev, Wt1[o * 512 + k], s1);
            s2 = fmaf(ev, Wt2[o * 512 + k], s2);
        }
        #pragma unroll
        for (int off = 16; off; off >>= 1) {
            s1 += __shfl_down_sync(0xffffffffu, s1, off);
            s2 += __shfl_down_sync(0xffffffffu, s2, off);
        }
        if (lane == 0) {
            g_attr1[a * 512 + o] = tanhf(s1 + bt1[o]);
            g_attr2[a * 512 + o] = fmaxf(s2 + bt2[o], 0.f);
        }
    }
}

// ======================= HMMA fused conv+BN+tanh+attn dot ===================
#define ST_A   10240
#define ST_B   4608
#define ST_BYTES (ST_A + ST_B)        // 14848
#define CONV_SMEM (3 * ST_BYTES)      // 44544

__global__ void __launch_bounds__(128, 4) conv_att_hmma(const int* __restrict__ cidx) {
    extern __shared__ char smem[];
    uint32_t sb = smem_u32(smem);
    int tid = threadIdx.x, wid = tid >> 5, lane = tid & 31;
    int wm = wid & 1, wn = wid >> 1;
    int m0 = blockIdx.x * 128;
    int n0 = blockIdx.y * 64;

    uint32_t a_soff[4], a_doff[4];
    #pragma unroll
    for (int t = 0; t < 4; t++) {
        int i = t * 128 + tid;
        int row = i >> 2, ch = i & 3;
        a_soff[t] = (uint32_t)((m0 + row) * CIN + ch * 8);
        a_doff[t] = (uint32_t)(row * 80 + ch * 16);
    }
    uint32_t b_soff[2], b_doff[2];
    #pragma unroll
    for (int t = 0; t < 2; t++) {
        int i = t * 128 + tid;
        int krow = i >> 3, bch = i & 7;
        b_soff[t] = (uint32_t)krow * NCOL + (uint32_t)(n0 + bch * 8);
        b_doff[t] = ST_A + (uint32_t)(krow * 144 + bch * 16);
    }

    float acc[4][4][4];
    #pragma unroll
    for (int mi = 0; mi < 4; mi++)
        #pragma unroll
        for (int nj = 0; nj < 4; nj++)
            #pragma unroll
            for (int r = 0; r < 4; r++) acc[mi][nj][r] = 0.f;

    uint32_t a_lds = sb + (uint32_t)(wm * 64 + (lane & 15)) * 80 + ((lane >> 4) & 1) * 16;
    uint32_t b_lds = sb + ST_A + (uint32_t)(lane & 15) * 144 +
                     (uint32_t)(wn * 32 + ((lane >> 4) & 1) * 8) * 2;

    #pragma unroll
    for (int st = 0; st < 2; st++) {
        uint32_t buf = (uint32_t)st * ST_BYTES;
        uint32_t ka = (uint32_t)st * 32;
        size_t kb = (size_t)st * 32 * NCOL;
        #pragma unroll
        for (int t = 0; t < 4; t++) CP_ASYNC16(sb + a_doff[t] + buf, g_Wc_h + a_soff[t] + ka);
        #pragma unroll
        for (int t = 0; t < 2; t++) CP_ASYNC16(sb + b_doff[t] + buf, g_xh + b_soff[t] + kb);
        CP_COMMIT();
    }

    int cstage = 0;
    for (int s = 0; s < 32; s++) {
        if (s < 31) { CP_WAIT(1); } else { CP_WAIT(0); }
        __syncthreads();

        if (s < 30) {
            int pst = cstage + 2; if (pst >= 3) pst -= 3;
            uint32_t buf = (uint32_t)pst * ST_BYTES;
            uint32_t ka = (uint32_t)(s + 2) * 32;
            size_t kb = (size_t)(s + 2) * 32 * NCOL;
            #pragma unroll
            for (int t = 0; t < 4; t++) CP_ASYNC16(sb + a_doff[t] + buf, g_Wc_h + a_soff[t] + ka);
            #pragma unroll
            for (int t = 0; t < 2; t++) CP_ASYNC16(sb + b_doff[t] + buf, g_xh + b_soff[t] + kb);
            CP_COMMIT();
        }

        uint32_t cbuf = (uint32_t)cstage * ST_BYTES;
        #pragma unroll
        for (int ks = 0; ks < 2; ks++) {
            uint32_t b0[4], b1[4];
            uint32_t baddr = b_lds + cbuf + (uint32_t)(ks * 16) * 144;
            LDSM_X4T(b0[0], b0[1], b0[2], b0[3], baddr);
            LDSM_X4T(b1[0], b1[1], b1[2], b1[3], baddr + 32);
            #pragma unroll
            for (int mi = 0; mi < 4; mi++) {
                uint32_t ah[4];
                uint32_t aaddr = a_lds + cbuf + (uint32_t)(mi * 16) * 80 + ks * 32;
                LDSM_X4(ah[0], ah[1], ah[2], ah[3], aaddr);
                MMA16816(acc[mi][0], ah, b0[0], b0[1]);
                MMA16816(acc[mi][1], ah, b0[2], b0[3]);
                MMA16816(acc[mi][2], ah, b1[0], b1[1]);
                MMA16816(acc[mi][3], ah, b1[2], b1[3]);
            }
        }
        if (++cstage == 3) cstage = 0;
    }
    __syncthreads();

    int b0i = n0 / HW2;
    int ncut = (b0i + 1) * HW2;
    int b1i = (ncut < n0 + 64) ? b0i + 1 : b0i;
    int c0i = cidx[b0i], c1i = cidx[b1i];
    int r0 = lane >> 2;
    int colE = (lane & 3) * 2;

    float accE[4] = {0.f, 0.f, 0.f, 0.f}, accO[4] = {0.f, 0.f, 0.f, 0.f};
    #pragma unroll
    for (int mi = 0; mi < 4; mi++) {
        int mA = m0 + wm * 64 + mi * 16 + r0;
        int mB = mA + 8;
        float biA = g_bi[mA], biB = g_bi[mB];
        float a0A = g_attr1[c0i * 512 + mA], a1A = g_attr1[c1i * 512 + mA];
        float a0B = g_attr1[c0i * 512 + mB], a1B = g_attr1[c1i * 512 + mB];
        #pragma unroll
        for (int nj = 0; nj < 4; nj++) {
            int colg = n0 + wn * 32 + nj * 8 + colE;
            float awAe = (colg < ncut) ? a0A : a1A;
            float awBe = (colg < ncut) ? a0B : a1B;
            float awAo = (colg + 1 < ncut) ? a0A : a1A;
            float awBo = (colg + 1 < ncut) ? a0B : a1B;
            accE[nj] += awAe * ftanh(acc[mi][nj][0] + biA) + awBe * ftanh(acc[mi][nj][2] + biB);
            accO[nj] += awAo * ftanh(acc[mi][nj][1] + biA) + awBo * ftanh(acc[mi][nj][3] + biB);
        }
    }
    #pragma unroll
    for (int off = 4; off <= 16; off <<= 1) {
        #pragma unroll
        for (int nj = 0; nj < 4; nj++) {
            accE[nj] += __shfl_xor_sync(0xffffffffu, accE[nj], off);
            accO[nj] += __shfl_xor_sync(0xffffffffu, accO[nj], off);
        }
    }
    float* sred = (float*)smem;
    if (lane < 4) {
        #pragma unroll
        for (int nj = 0; nj < 4; nj++) {
            sred[wid * 32 + nj * 8 + colE]     = accE[nj];
            sred[wid * 32 + nj * 8 + colE + 1] = accO[nj];
        }
    }
    __syncthreads();
    if (tid < 64) {
        int wnf = tid >> 5, cl = tid & 31;
        float t = sred[(wnf * 2) * 32 + cl] + sred[(wnf * 2 + 1) * 32 + cl];
        atomicAdd(&g_attlog[n0 + tid], t);
    }
}

// ==== fused softmax + feat + G1-input build (feat | attr2) ==================
__global__ void feat_kernel(const int* __restrict__ cidx) {
    int b = blockIdx.x, tid = threadIdx.x;
    __shared__ float sh[256];
    __shared__ float p[HW2];
    // softmax over 196 logits
    float v = (tid < HW2) ? g_attlog[b * HW2 + tid] * 0.044194173824159216f : -1e30f;
    sh[tid] = v;
    __syncthreads();
    for (int s = 128; s; s >>= 1) {
        if (tid < s) sh[tid] = fmaxf(sh[tid], sh[tid + s]);
        __syncthreads();
    }
    float mx = sh[0];
    __syncthreads();
    float e = (tid < HW2) ? __expf(v - mx) : 0.f;
    sh[tid] = e;
    __syncthreads();
    for (int s = 128; s; s >>= 1) {
        if (tid < s) sh[tid] += sh[tid + s];
        __syncthreads();
    }
    float inv = 1.f / sh[0];
    if (tid < HW2) p[tid] = e * inv;
    __syncthreads();

    // feat: dot x rows with p (fp16 x^T copy), write fp32 + hi/lo concat input
    int warp = tid >> 5, lane = tid & 31;
    const __half* xb = g_xh + (size_t)b * HW2;
    for (int k = warp; k < CIN; k += 8) {
        const __half* row = xb + (size_t)k * NCOL;
        float sum = 0.f;
        #pragma unroll
        for (int ch = lane; ch < 49; ch += 32) {
            uint2 u = *(const uint2*)(row + ch * 4);
            float2 f01 = __half22float2(*(__half2*)&u.x);
            float2 f23 = __half22float2(*(__half2*)&u.y);
            int hw = ch * 4;
            sum = fmaf(f01.x, p[hw + 0], sum);
            sum = fmaf(f01.y, p[hw + 1], sum);
            sum = fmaf(f23.x, p[hw + 2], sum);
            sum = fmaf(f23.y, p[hw + 3], sum);
        }
        #pragma unroll
        for (int off = 16; off; off >>= 1)
            sum += __shfl_down_sync(0xffffffffu, sum, off);
        if (lane == 0) {
            g_feat[b * CIN + k] = sum;
            __half h, l;
            split16(sum, h, l);
            g_in1h[b * 1536 + k] = h;
            g_in1l[b * 1536 + k] = l;
        }
    }
    // attr2 tail of concat input
    int ci = cidx[b];
    for (int j = tid; j < 512; j += 256) {
        float a = g_attr2[ci * 512 + j];
        __half h, l;
        split16(a, h, l);
        g_in1h[b * 1536 + 1024 + j] = h;
        g_in1l[b * 1536 + 1024 + j] = l;
    }
}

// =========== HMMA tail GEMM: C = act(A @ W^T + bias), 3-product split =======
// CTA 32M x 64N, 128 threads, 4 warps of 32M x 16N; K chunk 32, 3-stage.
// smem stage: Ah[32x80] Al[32x80] Wh[64x80] Wl[64x80] = 15360 B; x3 = 46080.
// EPI 0: A=g_in1 K=1536 N=512  -> relu    -> g_h1h/l
// EPI 1: A=g_h1  K=512  N=1024 -> sigmoid*g_feat -> g_fmh/l
// EPI 2: A=g_fm  K=1024 N=1024 -> +bias fp32 -> outp
#define GT_STAGE 15360
template <int EPI, int N, int K>
__global__ void __launch_bounds__(128, 4) gemmH_kernel(const float* __restrict__ bias,
                                                       float* __restrict__ outp) {
    const __half* Ah = (EPI == 0) ? g_in1h : (EPI == 1) ? g_h1h : g_fmh;
    const __half* Al = (EPI == 0) ? g_in1l : (EPI == 1) ? g_h1l : g_fml;
    const __half* Wh = (EPI == 0) ? g_w1h : (EPI == 1) ? g_w2h : g_w3h;
    const __half* Wl = (EPI == 0) ? g_w1l : (EPI == 1) ? g_w2l : g_w3l;

    extern __shared__ char smem[];
    uint32_t sb = smem_u32(smem);
    int tid = threadIdx.x, wid = tid >> 5, lane = tid & 31;
    int n0 = blockIdx.x * 64;
    int m0 = blockIdx.y * 32;

    // cp.async per-thread assignments
    int aRow = tid >> 2, aCh = tid & 3;
    const __half* srcAh = Ah + (size_t)(m0 + aRow) * K + aCh * 8;
    const __half* srcAl = Al + (size_t)(m0 + aRow) * K + aCh * 8;
    uint32_t dstAh = (uint32_t)(aRow * 80 + aCh * 16);
    uint32_t dstAl = 2560 + dstAh;
    const __half* srcWh0 = Wh + (size_t)(n0 + aRow) * K + aCh * 8;
    const __half* srcWh1 = Wh + (size_t)(n0 + 32 + aRow) * K + aCh * 8;
    const __half* srcWl0 = Wl + (size_t)(n0 + aRow) * K + aCh * 8;
    const __half* srcWl1 = Wl + (size_t)(n0 + 32 + aRow) * K + aCh * 8;
    uint32_t dstWh0 = 5120 + (uint32_t)(aRow * 80 + aCh * 16);
    uint32_t dstWh1 = dstWh0 + 32 * 80;
    uint32_t dstWl0 = dstWh0 + 5120;
    uint32_t dstWl1 = dstWh1 + 5120;

    float acc[2][2][4];
    #pragma unroll
    for (int mi = 0; mi < 2; mi++)
        #pragma unroll
        for (int nj = 0; nj < 2; nj++)
            #pragma unroll
            for (int r = 0; r < 4; r++) acc[mi][nj][r] = 0.f;

    uint32_t a_lds = sb + (uint32_t)(lane & 15) * 80 + ((lane >> 4) & 1) * 16;
    uint32_t w_lds = sb + 5120 + (uint32_t)(wid * 16 + (lane & 15)) * 80 + ((lane >> 4) & 1) * 16;

    const int NC = K / 32;
    #pragma unroll
    for (int st = 0; st < 2; st++) {
        uint32_t buf = (uint32_t)st * GT_STAGE;
        uint32_t ka = (uint32_t)st * 32;
        CP_ASYNC16(dstAh + sb + buf, srcAh + ka);
        CP_ASYNC16(dstAl + sb + buf, srcAl + ka);
        CP_ASYNC16(dstWh0 + sb + buf, srcWh0 + ka);
        CP_ASYNC16(dstWh1 + sb + buf, srcWh1 + ka);
        CP_ASYNC16(dstWl0 + sb + buf, srcWl0 + ka);
        CP_ASYNC16(dstWl1 + sb + buf, srcWl1 + ka);
        CP_COMMIT();
    }

    int cstage = 0;
    for (int s = 0; s < NC; s++) {
        if (s < NC - 1) { CP_WAIT(1); } else { CP_WAIT(0); }
        __syncthreads();

        if (s < NC - 2) {
            int pst = cstage + 2; if (pst >= 3) pst -= 3;
            uint32_t buf = (uint32_t)pst * GT_STAGE;
            uint32_t ka = (uint32_t)(s + 2) * 32;
            CP_ASYNC16(dstAh + sb + buf, srcAh + ka);
            CP_ASYNC16(dstAl + sb + buf, srcAl + ka);
            CP_ASYNC16(dstWh0 + sb + buf, srcWh0 + ka);
            CP_ASYNC16(dstWh1 + sb + buf, srcWh1 + ka);
            CP_ASYNC16(dstWl0 + sb + buf, srcWl0 + ka);
            CP_ASYNC16(dstWl1 + sb + buf, srcWl1 + ka);
            CP_COMMIT();
        }

        uint32_t cbuf = (uint32_t)cstage * GT_STAGE;
        #pragma unroll
        for (int ks = 0; ks < 2; ks++) {
            uint32_t wh[4], wl[4];
            uint32_t waddr = w_lds + cbuf + ks * 32;
            LDSM_X4(wh[0], wh[1], wh[2], wh[3], waddr);
            LDSM_X4(wl[0], wl[1], wl[2], wl[3], waddr + 5120);
            #pragma unroll
            for (int mi = 0; mi < 2; mi++) {
                uint32_t ah[4], al[4];
                uint32_t aaddr = a_lds + cbuf + (uint32_t)(mi * 16) * 80 + ks * 32;
                LDSM_X4(ah[0], ah[1], ah[2], ah[3], aaddr);
                LDSM_X4(al[0], al[1], al[2], al[3], aaddr + 2560);
                MMA16816(acc[mi][0], ah, wh[0], wh[2]);
                MMA16816(acc[mi][1], ah, wh[1], wh[3]);
                MMA16816(acc[mi][0], ah, wl[0], wl[2]);
                MMA16816(acc[mi][1], ah, wl[1], wl[3]);
                MMA16816(acc[mi][0], al, wh[0], wh[2]);
                MMA16816(acc[mi][1], al, wh[1], wh[3]);
            }
        }
        if (++cstage == 3) cstage = 0;
    }

    // ---- epilogue ----
    int r0 = lane >> 2;
    int cb = (lane & 3) * 2;
    #pragma unroll
    for (int nj = 0; nj < 2; nj++) {
        int gcol = n0 + wid * 16 + nj * 8 + cb;
        float bv0 = bias[gcol], bv1 = bias[gcol + 1];
        #pragma unroll
        for (int mi = 0; mi < 2; mi++) {
            #pragma unroll
            for (int rh = 0; rh < 2; rh++) {
                int row = m0 + mi * 16 + r0 + rh * 8;
                float v0 = acc[mi][nj][rh * 2 + 0] + bv0;
                float v1 = acc[mi][nj][rh * 2 + 1] + bv1;
                if (EPI == 0) {
                    v0 = fmaxf(v0, 0.f); v1 = fmaxf(v1, 0.f);
                    __half h0, l0, h1, l1;
                    split16(v0, h0, l0); split16(v1, h1, l1);
                    *(__half2*)(g_h1h + (size_t)row * N + gcol) = __halves2half2(h0, h1);
                    *(__half2*)(g_h1l + (size_t)row * N + gcol) = __halves2half2(l0, l1);
                } else if (EPI == 1) {
                    float s0 = 1.f / (1.f + __expf(-v0));
                    float s1 = 1.f / (1.f + __expf(-v1));
                    float p0 = s0 * g_feat[(size_t)row * 1024 + gcol];
                    float p1 = s1 * g_feat[(size_t)row * 1024 + gcol + 1];
                    __half h0, l0, h1, l1;
                    split16(p0, h0, l0); split16(p1, h1, l1);
                    *(__half2*)(g_fmh + (size_t)row * N + gcol) = __halves2half2(h0, h1);
                    *(__half2*)(g_fml + (size_t)row * N + gcol) = __halves2half2(l0, l1);
                } else {
                    *(float2*)(outp + (size_t)row * N + gcol) = make_float2(v0, v1);
                }
            }
        }
    }
}

// ---------------- row-wise L2 normalize in place ----------------------------
__global__ void l2norm_kernel(float* __restrict__ out) {
    int b = blockIdx.x, tid = threadIdx.x;
    __shared__ float sh[256];
    float s = 0.f;
    for (int i = tid; i < EMBD; i += 256) {
        float v = out[(size_t)b * EMBD + i];
        s = fmaf(v, v, s);
    }
    sh[tid] = s;
    __syncthreads();
    for (int st = 128; st; st >>= 1) {
        if (tid < st) sh[tid] += sh[tid + st];
        __syncthreads();
    }
    float inv = 1.f / sqrtf(sh[0]);
    for (int i = tid; i < EMBD; i += 256) out[(size_t)b * EMBD + i] *= inv;
}

// ---------------- launch ----------------------------------------------------
extern "C" void kernel_launch(void* const* d_in, const int* in_sizes, int n_in,
                              void* d_out, int out_size) {
    const float* x        = (const float*)d_in[0];
    const int*   c        = (const int*)  d_in[1];
    const float* attr_emb = (const float*)d_in[2];
    const float* Wt1      = (const float*)d_in[3];
    const float* bt1      = (const float*)d_in[4];
    const float* Wc       = (const float*)d_in[5];
    const float* bc       = (const float*)d_in[6];
    const float* bn_gamma = (const float*)d_in[7];
    const float* bn_beta  = (const float*)d_in[8];
    const float* bn_mean  = (const float*)d_in[9];
    const float* bn_var   = (const float*)d_in[10];
    const float* Wt2      = (const float*)d_in[11];
    const float* bt2      = (const float*)d_in[12];
    const float* W1       = (const float*)d_in[13];
    const float* b1       = (const float*)d_in[14];
    const float* W2       = (const float*)d_in[15];
    const float* b2       = (const float*)d_in[16];
    const float* Wf       = (const float*)d_in[17];
    const float* bf       = (const float*)d_in[18];
    float* out = (float*)d_out;

    static bool attr_set = false;
    if (!attr_set) {
        cudaFuncSetAttribute(conv_att_hmma, cudaFuncAttributeMaxDynamicSharedMemorySize, CONV_SMEM);
        attr_set = true;
    }

    wc_prep_kernel<<<CMID, 256>>>(Wc, bc, bn_gamma, bn_beta, bn_mean, bn_var);
    x_prep_kernel<<<BATCH * CIN * 49 / 256, 256>>>(x);
    attr_kernel<<<8, 256>>>(attr_emb, Wt1, bt1, Wt2, bt2);
    conv_att_hmma<<<dim3(4, NCOL / 64), 128, CONV_SMEM>>>(c);   // 4th launch -> ncu target
    wsplit_kernel<0><<<512 * 1536 / 1024, 256>>>(W1);
    wsplit_kernel<1><<<1024 * 512 / 1024, 256>>>(W2);
    wsplit_kernel<2><<<1024 * 1024 / 1024, 256>>>(Wf);
    feat_kernel<<<BATCH, 256>>>(c);
    gemmH_kernel<0, 512, 1536><<<dim3(512 / 64, BATCH / 32), 128, 3 * GT_STAGE>>>(b1, nullptr);
    gemmH_kernel<1, 1024, 512><<<dim3(1024 / 64, BATCH / 32), 128, 3 * GT_STAGE>>>(b2, nullptr);
    gemmH_kernel<2, 1024, 1024><<<dim3(1024 / 64, BATCH / 32), 128, 3 * GT_STAGE>>>(bf, out);
    l2norm_kernel<<<BATCH, 256>>>(out);
}

// round 9
// speedup vs baseline: 4.1089x; 1.0674x over previous
#include <cuda_runtime.h>
#include <cuda_fp16.h>
#include <math.h>
#include <stdint.h>

#define BATCH 512
#define CIN   1024
#define CMID  512
#define HW2   196
#define EMBD  1024
#define NCOL  (BATCH * HW2)   // 100352 = 784 * 128

// ---------------- scratch (device globals; no allocations allowed) ----------
__device__ float g_attr1[8 * 512];
__device__ float g_attr2[8 * 512];
__device__ float g_attlog[NCOL];
__device__ float g_feat[BATCH * 1024];
__device__ float g_bi[CMID];
__device__ __align__(16) __half g_Wc_h[CMID * CIN];
__device__ __align__(16) __half g_xh[(size_t)CIN * NCOL];   // x^T [K][N] fp16
// tail-GEMM weights, fp16 hi/lo
__device__ __align__(16) __half g_w1h[512 * 1536], g_w1l[512 * 1536];
__device__ __align__(16) __half g_w2h[1024 * 512], g_w2l[1024 * 512];
__device__ __align__(16) __half g_w3h[1024 * 1024], g_w3l[1024 * 1024];
// tail-GEMM activations, fp16 hi/lo
__device__ __align__(16) __half g_in1h[512 * 1536], g_in1l[512 * 1536];
__device__ __align__(16) __half g_h1h[512 * 512],  g_h1l[512 * 512];
__device__ __align__(16) __half g_fmh[512 * 1024], g_fml[512 * 1024];

// ======================= PTX helpers (non-'a' features only) ================
__device__ __forceinline__ uint32_t smem_u32(const void* p) {
    uint32_t a;
    asm("{ .reg .u64 t; cvta.to.shared.u64 t, %1; cvt.u32.u64 %0, t; }" : "=r"(a) : "l"(p));
    return a;
}
#define CP_ASYNC16(dst, src) \
    asm volatile("cp.async.cg.shared.global [%0], [%1], 16;" :: "r"(dst), "l"(src) : "memory")
#define CP_COMMIT() asm volatile("cp.async.commit_group;" ::: "memory")
#define CP_WAIT(n)  asm volatile("cp.async.wait_group %0;" :: "n"(n) : "memory")

#define LDSM_X4(r0, r1, r2, r3, addr) \
    asm volatile("ldmatrix.sync.aligned.m8n8.x4.shared.b16 {%0,%1,%2,%3}, [%4];" \
                 : "=r"(r0), "=r"(r1), "=r"(r2), "=r"(r3) : "r"(addr))
#define LDSM_X4T(r0, r1, r2, r3, addr) \
    asm volatile("ldmatrix.sync.aligned.m8n8.x4.trans.shared.b16 {%0,%1,%2,%3}, [%4];" \
                 : "=r"(r0), "=r"(r1), "=r"(r2), "=r"(r3) : "r"(addr))

#define MMA16816(C, A, B0, B1) \
    asm volatile("mma.sync.aligned.m16n8k16.row.col.f32.f16.f16.f32 " \
                 "{%0,%1,%2,%3},{%4,%5,%6,%7},{%8,%9},{%0,%1,%2,%3};" \
                 : "+f"((C)[0]), "+f"((C)[1]), "+f"((C)[2]), "+f"((C)[3]) \
                 : "r"((A)[0]), "r"((A)[1]), "r"((A)[2]), "r"((A)[3]), "r"(B0), "r"(B1))

__device__ __forceinline__ float ftanh(float x) {
    x = fminf(fmaxf(x, -12.f), 12.f);
    float e = __expf(2.f * x);
    return __fdividef(e - 1.f, e + 1.f);
}
__device__ __forceinline__ void split16(float v, __half& h, __half& l) {
    h = __float2half_rn(v);
    l = __float2half_rn(v - __half2float(h));
}

// ====== prep 1: fold BN scale into Wc -> fp16; ALSO zero g_attlog ===========
__global__ void wc_prep_kernel(const float* __restrict__ Wc, const float* __restrict__ bc,
                               const float* __restrict__ gamma, const float* __restrict__ beta,
                               const float* __restrict__ mean, const float* __restrict__ var) {
    int o = blockIdx.x, tid = threadIdx.x;
    int zi = o * 256 + tid;
    if (zi < NCOL) g_attlog[zi] = 0.f;
    float sc = gamma[o] * rsqrtf(var[o] + 1e-5f);
    if (tid == 0) g_bi[o] = (bc[o] - mean[o]) * sc + beta[o];
    float4 v = ((const float4*)(Wc + (size_t)o * CIN))[tid];
    __half2 h01 = __floats2half2_rn(v.x * sc, v.y * sc);
    __half2 h23 = __floats2half2_rn(v.z * sc, v.w * sc);
    uint2 u;
    u.x = *(uint32_t*)&h01;
    u.y = *(uint32_t*)&h23;
    ((uint2*)g_Wc_h)[o * 256 + tid] = u;
}

// ====== prep 2: transpose x to [K][N] fp16 ==================================
__global__ void x_prep_kernel(const float* __restrict__ x) {
    int g = blockIdx.x * 256 + threadIdx.x;
    int row = g / 49;
    int q = g - row * 49;
    int b = row >> 10, k = row & 1023;
    float4 v = ((const float4*)x)[(size_t)row * 49 + q];
    __half2 h01 = __floats2half2_rn(v.x, v.y);
    __half2 h23 = __floats2half2_rn(v.z, v.w);
    uint2 u;
    u.x = *(uint32_t*)&h01;
    u.y = *(uint32_t*)&h23;
    *(uint2*)(g_xh + (size_t)k * NCOL + b * HW2 + q * 4) = u;
}

// ====== prep 3: split tail weights into fp16 hi/lo (one merged launch) ======
__global__ void wsplit_kernel(const float* __restrict__ W1, const float* __restrict__ W2,
                              const float* __restrict__ W3) {
    int bid = blockIdx.x;
    const float* src;
    __half *dh, *dl;
    int i;
    if (bid < 768)        { src = W1; dh = g_w1h; dl = g_w1l; i = bid * 256 + threadIdx.x; }
    else if (bid < 1280)  { src = W2; dh = g_w2h; dl = g_w2l; i = (bid - 768) * 256 + threadIdx.x; }
    else                  { src = W3; dh = g_w3h; dl = g_w3l; i = (bid - 1280) * 256 + threadIdx.x; }
    float4 v = ((const float4*)src)[i];
    __half h0, h1, h2, h3, l0, l1, l2, l3;
    split16(v.x, h0, l0); split16(v.y, h1, l1);
    split16(v.z, h2, l2); split16(v.w, h3, l3);
    __half2 hh01 = __halves2half2(h0, h1), hh23 = __halves2half2(h2, h3);
    __half2 ll01 = __halves2half2(l0, l1), ll23 = __halves2half2(l2, l3);
    uint2 uh, ul;
    uh.x = *(uint32_t*)&hh01; uh.y = *(uint32_t*)&hh23;
    ul.x = *(uint32_t*)&ll01; ul.y = *(uint32_t*)&ll23;
    ((uint2*)dh)[i] = uh;
    ((uint2*)dl)[i] = ul;
}

// ---------------- attr tables: 8 x 512, tiny -------------------------------
__global__ void attr_kernel(const float* __restrict__ emb,
                            const float* __restrict__ Wt1, const float* __restrict__ bt1,
                            const float* __restrict__ Wt2, const float* __restrict__ bt2) {
    int a = blockIdx.x;
    __shared__ float e[512];
    int tid = threadIdx.x;
    e[tid]       = emb[a * 512 + tid];
    e[tid + 256] = emb[a * 512 + tid + 256];
    __syncthreads();
    int warp = tid >> 5, lane = tid & 31;
    for (int o = warp; o < 512; o += 8) {
        float s1 = 0.f, s2 = 0.f;
        for (int k = lane; k < 512; k += 32) {
            float ev = e[k];
            s1 = fmaf(ev, Wt1[o * 512 + k], s1);
            s2 = fmaf(ev, Wt2[o * 512 + k], s2);
        }
        #pragma unroll
        for (int off = 16; off; off >>= 1) {
            s1 += __shfl_down_sync(0xffffffffu, s1, off);
            s2 += __shfl_down_sync(0xffffffffu, s2, off);
        }
        if (lane == 0) {
            g_attr1[a * 512 + o] = tanhf(s1 + bt1[o]);
            g_attr2[a * 512 + o] = fmaxf(s2 + bt2[o], 0.f);
        }
    }
}

// ======================= HMMA fused conv+BN+tanh+attn dot ===================
// GEMM M=512(o) x N=100352 x K=1024, single fp16 product.
// Grid (4, 784): bx = 128-row M group (fast dim -> B tile L2-shared),
//                by = 128-col N tile.
// CTA: 128 threads, 4 warps 2(m) x 2(n); WARP TILE 64M x 64N; K chunk 32.
// 4-stage cp.async, one __syncthreads per chunk.
// smem stage: A[128x80B]=10240 + B[32x272B]=8704 = 18944; x4 = 75776 -> 2 CTA/SM.
#define ST_A   10240
#define ST_B   8704
#define ST_BYTES (ST_A + ST_B)        // 18944
#define CONV_SMEM (4 * ST_BYTES)      // 75776

__global__ void __launch_bounds__(128, 2) conv_att_hmma(const int* __restrict__ cidx) {
    extern __shared__ char smem[];
    uint32_t sb = smem_u32(smem);
    int tid = threadIdx.x, wid = tid >> 5, lane = tid & 31;
    int wm = wid & 1, wn = wid >> 1;
    int m0 = blockIdx.x * 128;
    int n0 = blockIdx.y * 128;

    // ---- cp.async offsets: A 4 x 16B, B 4 x 16B per thread ----
    uint32_t a_soff[4], a_doff[4];
    #pragma unroll
    for (int t = 0; t < 4; t++) {
        int i = t * 128 + tid;          // 0..511
        int row = i >> 2, ch = i & 3;
        a_soff[t] = (uint32_t)((m0 + row) * CIN + ch * 8);
        a_doff[t] = (uint32_t)(row * 80 + ch * 16);
    }
    uint32_t b_soff[4], b_doff[4];
    #pragma unroll
    for (int t = 0; t < 4; t++) {
        int i = t * 128 + tid;          // 0..511
        int krow = i >> 4, bch = i & 15;
        b_soff[t] = (uint32_t)krow * NCOL + (uint32_t)(n0 + bch * 8);
        b_doff[t] = ST_A + (uint32_t)(krow * 272 + bch * 16);
    }

    float acc[4][8][4];
    #pragma unroll
    for (int mi = 0; mi < 4; mi++)
        #pragma unroll
        for (int nj = 0; nj < 8; nj++)
            #pragma unroll
            for (int r = 0; r < 4; r++) acc[mi][nj][r] = 0.f;

    // ldmatrix bases
    uint32_t a_lds = sb + (uint32_t)(wm * 64 + (lane & 15)) * 80 + ((lane >> 4) & 1) * 16;
    uint32_t b_lds = sb + ST_A + (uint32_t)(lane & 15) * 272 +
                     (uint32_t)(wn * 64 + ((lane >> 4) & 1) * 8) * 2;

    // ---- prologue: stages 0..2 ----
    #pragma unroll
    for (int st = 0; st < 3; st++) {
        uint32_t buf = (uint32_t)st * ST_BYTES;
        uint32_t ka = (uint32_t)st * 32;
        size_t kb = (size_t)st * 32 * NCOL;
        #pragma unroll
        for (int t = 0; t < 4; t++) CP_ASYNC16(sb + a_doff[t] + buf, g_Wc_h + a_soff[t] + ka);
        #pragma unroll
        for (int t = 0; t < 4; t++) CP_ASYNC16(sb + b_doff[t] + buf, g_xh + b_soff[t] + kb);
        CP_COMMIT();
    }

    for (int s = 0; s < 32; s++) {
        if (s < 30) { CP_WAIT(2); } else if (s == 30) { CP_WAIT(1); } else { CP_WAIT(0); }
        __syncthreads();

        if (s < 29) {
            uint32_t buf = (uint32_t)((s + 3) & 3) * ST_BYTES;
            uint32_t ka = (uint32_t)(s + 3) * 32;
            size_t kb = (size_t)(s + 3) * 32 * NCOL;
            #pragma unroll
            for (int t = 0; t < 4; t++) CP_ASYNC16(sb + a_doff[t] + buf, g_Wc_h + a_soff[t] + ka);
            #pragma unroll
            for (int t = 0; t < 4; t++) CP_ASYNC16(sb + b_doff[t] + buf, g_xh + b_soff[t] + kb);
            CP_COMMIT();
        }

        uint32_t cbuf = (uint32_t)(s & 3) * ST_BYTES;
        #pragma unroll
        for (int ks = 0; ks < 2; ks++) {
            uint32_t bfr[4][4];
            uint32_t baddr = b_lds + cbuf + (uint32_t)(ks * 16) * 272;
            #pragma unroll
            for (int bq = 0; bq < 4; bq++)
                LDSM_X4T(bfr[bq][0], bfr[bq][1], bfr[bq][2], bfr[bq][3], baddr + bq * 32);
            #pragma unroll
            for (int mi = 0; mi < 4; mi++) {
                uint32_t ah[4];
                uint32_t aaddr = a_lds + cbuf + (uint32_t)(mi * 16) * 80 + ks * 32;
                LDSM_X4(ah[0], ah[1], ah[2], ah[3], aaddr);
                #pragma unroll
                for (int bq = 0; bq < 4; bq++) {
                    MMA16816(acc[mi][bq * 2 + 0], ah, bfr[bq][0], bfr[bq][1]);
                    MMA16816(acc[mi][bq * 2 + 1], ah, bfr[bq][2], bfr[bq][3]);
                }
            }
        }
    }
    __syncthreads();

    // ---- epilogue: logits[n] += sum_m attr1[c(n)][m] * tanh(D[m][n]+bi[m]) ----
    int b0i = n0 / HW2;
    int ncut = (b0i + 1) * HW2;
    int b1i = (ncut < n0 + 128) ? b0i + 1 : b0i;
    int c0i = cidx[b0i], c1i = cidx[b1i];
    int r0 = lane >> 2;
    int colE = (lane & 3) * 2;

    float accE[8], accO[8];
    #pragma unroll
    for (int nj = 0; nj < 8; nj++) { accE[nj] = 0.f; accO[nj] = 0.f; }
    #pragma unroll
    for (int mi = 0; mi < 4; mi++) {
        int mA = m0 + wm * 64 + mi * 16 + r0;
        int mB = mA + 8;
        float biA = g_bi[mA], biB = g_bi[mB];
        float a0A = g_attr1[c0i * 512 + mA], a1A = g_attr1[c1i * 512 + mA];
        float a0B = g_attr1[c0i * 512 + mB], a1B = g_attr1[c1i * 512 + mB];
        #pragma unroll
        for (int nj = 0; nj < 8; nj++) {
            int colg = n0 + wn * 64 + nj * 8 + colE;
            float awAe = (colg < ncut) ? a0A : a1A;
            float awBe = (colg < ncut) ? a0B : a1B;
            float awAo = (colg + 1 < ncut) ? a0A : a1A;
            float awBo = (colg + 1 < ncut) ? a0B : a1B;
            accE[nj] += awAe * ftanh(acc[mi][nj][0] + biA) + awBe * ftanh(acc[mi][nj][2] + biB);
            accO[nj] += awAo * ftanh(acc[mi][nj][1] + biA) + awBo * ftanh(acc[mi][nj][3] + biB);
        }
    }
    #pragma unroll
    for (int off = 4; off <= 16; off <<= 1) {
        #pragma unroll
        for (int nj = 0; nj < 8; nj++) {
            accE[nj] += __shfl_xor_sync(0xffffffffu, accE[nj], off);
            accO[nj] += __shfl_xor_sync(0xffffffffu, accO[nj], off);
        }
    }
    float* sred = (float*)smem;   // [4 warps][64 cols]
    if (lane < 4) {
        #pragma unroll
        for (int nj = 0; nj < 8; nj++) {
            sred[wid * 64 + nj * 8 + colE]     = accE[nj];
            sred[wid * 64 + nj * 8 + colE + 1] = accO[nj];
        }
    }
    __syncthreads();
    if (tid < 128) {
        int wn2 = tid >> 6, cl = tid & 63;
        float t = sred[(wn2 * 2) * 64 + cl] + sred[(wn2 * 2 + 1) * 64 + cl];
        atomicAdd(&g_attlog[n0 + tid], t);
    }
}

// ==== fused softmax + feat + G1-input build (feat | attr2) ==================
__global__ void feat_kernel(const int* __restrict__ cidx) {
    int b = blockIdx.x, tid = threadIdx.x;
    __shared__ float sh[256];
    __shared__ float p[HW2];
    float v = (tid < HW2) ? g_attlog[b * HW2 + tid] * 0.044194173824159216f : -1e30f;
    sh[tid] = v;
    __syncthreads();
    for (int s = 128; s; s >>= 1) {
        if (tid < s) sh[tid] = fmaxf(sh[tid], sh[tid + s]);
        __syncthreads();
    }
    float mx = sh[0];
    __syncthreads();
    float e = (tid < HW2) ? __expf(v - mx) : 0.f;
    sh[tid] = e;
    __syncthreads();
    for (int s = 128; s; s >>= 1) {
        if (tid < s) sh[tid] += sh[tid + s];
        __syncthreads();
    }
    float inv = 1.f / sh[0];
    if (tid < HW2) p[tid] = e * inv;
    __syncthreads();

    int warp = tid >> 5, lane = tid & 31;
    const __half* xb = g_xh + (size_t)b * HW2;
    for (int k = warp; k < CIN; k += 8) {
        const __half* row = xb + (size_t)k * NCOL;
        float sum = 0.f;
        #pragma unroll
        for (int ch = lane; ch < 49; ch += 32) {
            uint2 u = *(const uint2*)(row + ch * 4);
            float2 f01 = __half22float2(*(__half2*)&u.x);
            float2 f23 = __half22float2(*(__half2*)&u.y);
            int hw = ch * 4;
            sum = fmaf(f01.x, p[hw + 0], sum);
            sum = fmaf(f01.y, p[hw + 1], sum);
            sum = fmaf(f23.x, p[hw + 2], sum);
            sum = fmaf(f23.y, p[hw + 3], sum);
        }
        #pragma unroll
        for (int off = 16; off; off >>= 1)
            sum += __shfl_down_sync(0xffffffffu, sum, off);
        if (lane == 0) {
            g_feat[b * CIN + k] = sum;
            __half h, l;
            split16(sum, h, l);
            g_in1h[b * 1536 + k] = h;
            g_in1l[b * 1536 + k] = l;
        }
    }
    int ci = cidx[b];
    for (int j = tid; j < 512; j += 256) {
        float a = g_attr2[ci * 512 + j];
        __half h, l;
        split16(a, h, l);
        g_in1h[b * 1536 + 1024 + j] = h;
        g_in1l[b * 1536 + 1024 + j] = l;
    }
}

// =========== HMMA tail GEMM: C = act(A @ W^T + bias), 3-product split =======
#define GT_STAGE 15360
template <int EPI, int N, int K>
__global__ void __launch_bounds__(128, 4) gemmH_kernel(const float* __restrict__ bias,
                                                       float* __restrict__ outp) {
    const __half* Ah = (EPI == 0) ? g_in1h : (EPI == 1) ? g_h1h : g_fmh;
    const __half* Al = (EPI == 0) ? g_in1l : (EPI == 1) ? g_h1l : g_fml;
    const __half* Wh = (EPI == 0) ? g_w1h : (EPI == 1) ? g_w2h : g_w3h;
    const __half* Wl = (EPI == 0) ? g_w1l : (EPI == 1) ? g_w2l : g_w3l;

    extern __shared__ char smem[];
    uint32_t sb = smem_u32(smem);
    int tid = threadIdx.x, wid = tid >> 5, lane = tid & 31;
    int n0 = blockIdx.x * 64;
    int m0 = blockIdx.y * 32;

    int aRow = tid >> 2, aCh = tid & 3;
    const __half* srcAh = Ah + (size_t)(m0 + aRow) * K + aCh * 8;
    const __half* srcAl = Al + (size_t)(m0 + aRow) * K + aCh * 8;
    uint32_t dstAh = (uint32_t)(aRow * 80 + aCh * 16);
    uint32_t dstAl = 2560 + dstAh;
    const __half* srcWh0 = Wh + (size_t)(n0 + aRow) * K + aCh * 8;
    const __half* srcWh1 = Wh + (size_t)(n0 + 32 + aRow) * K + aCh * 8;
    const __half* srcWl0 = Wl + (size_t)(n0 + aRow) * K + aCh * 8;
    const __half* srcWl1 = Wl + (size_t)(n0 + 32 + aRow) * K + aCh * 8;
    uint32_t dstWh0 = 5120 + (uint32_t)(aRow * 80 + aCh * 16);
    uint32_t dstWh1 = dstWh0 + 32 * 80;
    uint32_t dstWl0 = dstWh0 + 5120;
    uint32_t dstWl1 = dstWh1 + 5120;

    float acc[2][2][4];
    #pragma unroll
    for (int mi = 0; mi < 2; mi++)
        #pragma unroll
        for (int nj = 0; nj < 2; nj++)
            #pragma unroll
            for (int r = 0; r < 4; r++) acc[mi][nj][r] = 0.f;

    uint32_t a_lds = sb + (uint32_t)(lane & 15) * 80 + ((lane >> 4) & 1) * 16;
    uint32_t w_lds = sb + 5120 + (uint32_t)(wid * 16 + (lane & 15)) * 80 + ((lane >> 4) & 1) * 16;

    const int NC = K / 32;
    #pragma unroll
    for (int st = 0; st < 2; st++) {
        uint32_t buf = (uint32_t)st * GT_STAGE;
        uint32_t ka = (uint32_t)st * 32;
        CP_ASYNC16(dstAh + sb + buf, srcAh + ka);
        CP_ASYNC16(dstAl + sb + buf, srcAl + ka);
        CP_ASYNC16(dstWh0 + sb + buf, srcWh0 + ka);
        CP_ASYNC16(dstWh1 + sb + buf, srcWh1 + ka);
        CP_ASYNC16(dstWl0 + sb + buf, srcWl0 + ka);
        CP_ASYNC16(dstWl1 + sb + buf, srcWl1 + ka);
        CP_COMMIT();
    }

    int cstage = 0;
    for (int s = 0; s < NC; s++) {
        if (s < NC - 1) { CP_WAIT(1); } else { CP_WAIT(0); }
        __syncthreads();

        if (s < NC - 2) {
            int pst = cstage + 2; if (pst >= 3) pst -= 3;
            uint32_t buf = (uint32_t)pst * GT_STAGE;
            uint32_t ka = (uint32_t)(s + 2) * 32;
            CP_ASYNC16(dstAh + sb + buf, srcAh + ka);
            CP_ASYNC16(dstAl + sb + buf, srcAl + ka);
            CP_ASYNC16(dstWh0 + sb + buf, srcWh0 + ka);
            CP_ASYNC16(dstWh1 + sb + buf, srcWh1 + ka);
            CP_ASYNC16(dstWl0 + sb + buf, srcWl0 + ka);
            CP_ASYNC16(dstWl1 + sb + buf, srcWl1 + ka);
            CP_COMMIT();
        }

        uint32_t cbuf = (uint32_t)cstage * GT_STAGE;
        #pragma unroll
        for (int ks = 0; ks < 2; ks++) {
            uint32_t wh[4], wl[4];
            uint32_t waddr = w_lds + cbuf + ks * 32;
            LDSM_X4(wh[0], wh[1], wh[2], wh[3], waddr);
            LDSM_X4(wl[0], wl[1], wl[2], wl[3], waddr + 5120);
            #pragma unroll
            for (int mi = 0; mi < 2; mi++) {
                uint32_t ah[4], al[4];
                uint32_t aaddr = a_lds + cbuf + (uint32_t)(mi * 16) * 80 + ks * 32;
                LDSM_X4(ah[0], ah[1], ah[2], ah[3], aaddr);
                LDSM_X4(al[0], al[1], al[2], al[3], aaddr + 2560);
                MMA16816(acc[mi][0], ah, wh[0], wh[2]);
                MMA16816(acc[mi][1], ah, wh[1], wh[3]);
                MMA16816(acc[mi][0], ah, wl[0], wl[2]);
                MMA16816(acc[mi][1], ah, wl[1], wl[3]);
                MMA16816(acc[mi][0], al, wh[0], wh[2]);
                MMA16816(acc[mi][1], al, wh[1], wh[3]);
            }
        }
        if (++cstage == 3) cstage = 0;
    }

    int r0 = lane >> 2;
    int cb = (lane & 3) * 2;
    #pragma unroll
    for (int nj = 0; nj < 2; nj++) {
        int gcol = n0 + wid * 16 + nj * 8 + cb;
        float bv0 = bias[gcol], bv1 = bias[gcol + 1];
        #pragma unroll
        for (int mi = 0; mi < 2; mi++) {
            #pragma unroll
            for (int rh = 0; rh < 2; rh++) {
                int row = m0 + mi * 16 + r0 + rh * 8;
                float v0 = acc[mi][nj][rh * 2 + 0] + bv0;
                float v1 = acc[mi][nj][rh * 2 + 1] + bv1;
                if (EPI == 0) {
                    v0 = fmaxf(v0, 0.f); v1 = fmaxf(v1, 0.f);
                    __half h0, l0, h1, l1;
                    split16(v0, h0, l0); split16(v1, h1, l1);
                    *(__half2*)(g_h1h + (size_t)row * N + gcol) = __halves2half2(h0, h1);
                    *(__half2*)(g_h1l + (size_t)row * N + gcol) = __halves2half2(l0, l1);
                } else if (EPI == 1) {
                    float s0 = 1.f / (1.f + __expf(-v0));
                    float s1 = 1.f / (1.f + __expf(-v1));
                    float p0 = s0 * g_feat[(size_t)row * 1024 + gcol];
                    float p1 = s1 * g_feat[(size_t)row * 1024 + gcol + 1];
                    __half h0, l0, h1, l1;
                    split16(p0, h0, l0); split16(p1, h1, l1);
                    *(__half2*)(g_fmh + (size_t)row * N + gcol) = __halves2half2(h0, h1);
                    *(__half2*)(g_fml + (size_t)row * N + gcol) = __halves2half2(l0, l1);
                } else {
                    *(float2*)(outp + (size_t)row * N + gcol) = make_float2(v0, v1);
                }
            }
        }
    }
}

// ---------------- row-wise L2 normalize in place ----------------------------
__global__ void l2norm_kernel(float* __restrict__ out) {
    int b = blockIdx.x, tid = threadIdx.x;
    __shared__ float sh[256];
    float s = 0.f;
    for (int i = tid; i < EMBD; i += 256) {
        float v = out[(size_t)b * EMBD + i];
        s = fmaf(v, v, s);
    }
    sh[tid] = s;
    __syncthreads();
    for (int st = 128; st; st >>= 1) {
        if (tid < st) sh[tid] += sh[tid + st];
        __syncthreads();
    }
    float inv = 1.f / sqrtf(sh[0]);
    for (int i = tid; i < EMBD; i += 256) out[(size_t)b * EMBD + i] *= inv;
}

// ---------------- launch ----------------------------------------------------
extern "C" void kernel_launch(void* const* d_in, const int* in_sizes, int n_in,
                              void* d_out, int out_size) {
    const float* x        = (const float*)d_in[0];
    const int*   c        = (const int*)  d_in[1];
    const float* attr_emb = (const float*)d_in[2];
    const float* Wt1      = (const float*)d_in[3];
    const float* bt1      = (const float*)d_in[4];
    const float* Wc       = (const float*)d_in[5];
    const float* bc       = (const float*)d_in[6];
    const float* bn_gamma = (const float*)d_in[7];
    const float* bn_beta  = (const float*)d_in[8];
    const float* bn_mean  = (const float*)d_in[9];
    const float* bn_var   = (const float*)d_in[10];
    const float* Wt2      = (const float*)d_in[11];
    const float* bt2      = (const float*)d_in[12];
    const float* W1       = (const float*)d_in[13];
    const float* b1       = (const float*)d_in[14];
    const float* W2       = (const float*)d_in[15];
    const float* b2       = (const float*)d_in[16];
    const float* Wf       = (const float*)d_in[17];
    const float* bf       = (const float*)d_in[18];
    float* out = (float*)d_out;

    static bool attr_set = false;
    if (!attr_set) {
        cudaFuncSetAttribute(conv_att_hmma, cudaFuncAttributeMaxDynamicSharedMemorySize, CONV_SMEM);
        attr_set = true;
    }

    wc_prep_kernel<<<CMID, 256>>>(Wc, bc, bn_gamma, bn_beta, bn_mean, bn_var);
    x_prep_kernel<<<BATCH * CIN * 49 / 256, 256>>>(x);
    attr_kernel<<<8, 256>>>(attr_emb, Wt1, bt1, Wt2, bt2);
    conv_att_hmma<<<dim3(4, NCOL / 128), 128, CONV_SMEM>>>(c);   // 4th launch -> ncu target
    wsplit_kernel<<<2304, 256>>>(W1, W2, Wf);
    feat_kernel<<<BATCH, 256>>>(c);
    gemmH_kernel<0, 512, 1536><<<dim3(512 / 64, BATCH / 32), 128, 3 * GT_STAGE>>>(b1, nullptr);
    gemmH_kernel<1, 1024, 512><<<dim3(1024 / 64, BATCH / 32), 128, 3 * GT_STAGE>>>(b2, nullptr);
    gemmH_kernel<2, 1024, 1024><<<dim3(1024 / 64, BATCH / 32), 128, 3 * GT_STAGE>>>(bf, out);
    l2norm_kernel<<<BATCH, 256>>>(out);
}